// round 2
// baseline (speedup 1.0000x reference)
#include <cuda_runtime.h>
#include <math.h>

// Problem constants
#define BB 8
#define TT 1024
#define CC 768
#define NHH 12
#define HDD 64

// Scratch (static __device__ arrays: no allocation allowed)
__device__ float g_v  [BB * TT * CC];                 // value projection [B,T,C]
__device__ float g_att0[(long long)BB * NHH * TT * TT]; // raw scores
__device__ float g_att2[(long long)BB * NHH * TT * TT]; // mixed scores / probs
__device__ float g_wcl[TT * TT];                      // Wc @ Wl
__device__ float g_y  [BB * TT * CC];                 // attention output [B,T,C]

// ---------------------------------------------------------------------------
// Generic batched tiled FP32 GEMM.
//   TB=true : C = alpha * A @ B^T + bias   (A: [M,K] lda, B: [N,K] ldb)
//   TB=false: C = alpha * A @ B   + bias   (A: [M,K] lda, B: [K,N] ldb)
// Batch index z -> (b = z / batchH, h = z % batchH); per-operand strides.
// CAUSAL_SKIP: skip output tiles entirely above the diagonal (n0 > m0+BM-1).
// Requires M%BM==0, N%BN==0, K%BK==0, lda/ldb/ldc %4==0, 16B-aligned offsets.
// ---------------------------------------------------------------------------
template<int BM, int BN, int BK, int TM, int TN, bool TB, bool CAUSAL_SKIP>
__global__ void __launch_bounds__((BM/TM)*(BN/TN))
gemm_k(const float* __restrict__ A, const float* __restrict__ Bm,
       const float* __restrict__ bias, float* __restrict__ Cm,
       int M, int N, int K, int lda, int ldb, int ldc,
       long long sAb, long long sAh, long long sBb, long long sBh,
       long long sCb, long long sCh, int batchH, float alpha)
{
    constexpr int THREADS = (BM/TM)*(BN/TN);
    const int z = blockIdx.z;
    const int b = z / batchH, h = z % batchH;
    const float* Ab = A  + b * sAb + h * sAh;
    const float* Bb = Bm + b * sBb + h * sBh;
    float*       Cb = Cm + b * sCb + h * sCh;

    const int m0 = blockIdx.y * BM;
    const int n0 = blockIdx.x * BN;
    if (CAUSAL_SKIP && n0 > m0 + BM - 1) return;   // fully-masked tile

    __shared__ float As[BK][BM];
    __shared__ float Bs[BK][BN];

    const int tid = threadIdx.x;
    float acc[TM][TN];
#pragma unroll
    for (int i = 0; i < TM; i++)
#pragma unroll
        for (int j = 0; j < TN; j++) acc[i][j] = 0.f;

    constexpr int A_VECS = BM * BK / 4;
    constexpr int A_PER  = A_VECS / THREADS;
    constexpr int B_VECS = BN * BK / 4;
    constexpr int B_PER  = B_VECS / THREADS;
    static_assert(A_PER * THREADS == A_VECS, "A tiling");
    static_assert(B_PER * THREADS == B_VECS, "B tiling");

    const int tr = (tid / (BN/TN)) * TM;
    const int tc = (tid % (BN/TN)) * TN;

    for (int k0 = 0; k0 < K; k0 += BK) {
        // --- load A tile: [BM x BK], vectorized along K, store transposed ---
#pragma unroll
        for (int i = 0; i < A_PER; i++) {
            int v   = tid + i * THREADS;
            int row = v / (BK/4);
            int kc  = (v % (BK/4)) * 4;
            float4 t = *reinterpret_cast<const float4*>(
                &Ab[(long long)(m0 + row) * lda + k0 + kc]);
            As[kc+0][row] = t.x; As[kc+1][row] = t.y;
            As[kc+2][row] = t.z; As[kc+3][row] = t.w;
        }
        // --- load B tile ---
        if constexpr (TB) {
#pragma unroll
            for (int i = 0; i < B_PER; i++) {
                int v   = tid + i * THREADS;
                int row = v / (BK/4);          // n-index
                int kc  = (v % (BK/4)) * 4;
                float4 t = *reinterpret_cast<const float4*>(
                    &Bb[(long long)(n0 + row) * ldb + k0 + kc]);
                Bs[kc+0][row] = t.x; Bs[kc+1][row] = t.y;
                Bs[kc+2][row] = t.z; Bs[kc+3][row] = t.w;
            }
        } else {
#pragma unroll
            for (int i = 0; i < B_PER; i++) {
                int v    = tid + i * THREADS;
                int krow = v / (BN/4);
                int nc   = (v % (BN/4)) * 4;
                float4 t = *reinterpret_cast<const float4*>(
                    &Bb[(long long)(k0 + krow) * ldb + n0 + nc]);
                *reinterpret_cast<float4*>(&Bs[krow][nc]) = t;
            }
        }
        __syncthreads();

        // --- compute 8x8 (or 8x4) outer products ---
#pragma unroll
        for (int kk = 0; kk < BK; kk++) {
            float ar[TM], br[TN];
#pragma unroll
            for (int i = 0; i < TM; i++) ar[i] = As[kk][tr + i];
#pragma unroll
            for (int j = 0; j < TN; j++) br[j] = Bs[kk][tc + j];
#pragma unroll
            for (int i = 0; i < TM; i++)
#pragma unroll
                for (int j = 0; j < TN; j++)
                    acc[i][j] += ar[i] * br[j];
        }
        __syncthreads();
    }

    // --- epilogue: alpha scale + optional bias, float4 stores ---
#pragma unroll
    for (int i = 0; i < TM; i++) {
        long long crow = (long long)(m0 + tr + i) * ldc + n0 + tc;
#pragma unroll
        for (int j = 0; j < TN; j += 4) {
            float4 t;
            t.x = acc[i][j+0] * alpha + (bias ? bias[n0 + tc + j + 0] : 0.f);
            t.y = acc[i][j+1] * alpha + (bias ? bias[n0 + tc + j + 1] : 0.f);
            t.z = acc[i][j+2] * alpha + (bias ? bias[n0 + tc + j + 2] : 0.f);
            t.w = acc[i][j+3] * alpha + (bias ? bias[n0 + tc + j + 3] : 0.f);
            *reinterpret_cast<float4*>(&Cb[crow + j]) = t;
        }
    }
}

// ---------------------------------------------------------------------------
// In-place causal softmax over rows of att [Z, T, T]; valid length = q+1.
// Masked entries (j > q) written as exact 0 (matches exp(-1e9 - max) == 0).
// ---------------------------------------------------------------------------
__device__ __forceinline__ float warp_max(float v) {
#pragma unroll
    for (int o = 16; o; o >>= 1) v = fmaxf(v, __shfl_xor_sync(0xffffffffu, v, o));
    return v;
}
__device__ __forceinline__ float warp_sum(float v) {
#pragma unroll
    for (int o = 16; o; o >>= 1) v += __shfl_xor_sync(0xffffffffu, v, o);
    return v;
}

__global__ void softmax_causal_k(float* __restrict__ att)
{
    const long long z = blockIdx.y;
    const int q = blockIdx.x;
    float* row = att + (z * TT + q) * (long long)TT;
    const int L = q + 1;
    const int tid = threadIdx.x;
    __shared__ float red[8];

    // max over valid region
    float m = -INFINITY;
    for (int j = tid; j < L; j += blockDim.x) m = fmaxf(m, row[j]);
    m = warp_max(m);
    if ((tid & 31) == 0) red[tid >> 5] = m;
    __syncthreads();
    if (tid < 32) {
        float v = (tid < 8) ? red[tid] : -INFINITY;
        v = warp_max(v);
        if (tid == 0) red[0] = v;
    }
    __syncthreads();
    const float mg = red[0];
    __syncthreads();

    // sum of exp
    float s = 0.f;
    for (int j = tid; j < L; j += blockDim.x) s += __expf(row[j] - mg);
    s = warp_sum(s);
    if ((tid & 31) == 0) red[tid >> 5] = s;
    __syncthreads();
    if (tid < 32) {
        float v = (tid < 8) ? red[tid] : 0.f;
        v = warp_sum(v);
        if (tid == 0) red[0] = v;
    }
    __syncthreads();
    const float inv = 1.f / red[0];

    for (int j = tid; j < TT; j += blockDim.x)
        row[j] = (j < L) ? __expf(row[j] - mg) * inv : 0.f;
}

// ---------------------------------------------------------------------------
extern "C" void kernel_launch(void* const* d_in, const int* in_sizes, int n_in,
                              void* d_out, int out_size)
{
    const float* x  = (const float*)d_in[0];
    const float* Wv = (const float*)d_in[1];
    const float* bv = (const float*)d_in[2];
    const float* Wl = (const float*)d_in[3];
    const float* Wc = (const float*)d_in[4];
    const float* bc = (const float*)d_in[5];
    const float* Wp = (const float*)d_in[6];
    const float* bp = (const float*)d_in[7];
    float* out = (float*)d_out;

    float *v_p, *att0_p, *att2_p, *wcl_p, *y_p;
    cudaGetSymbolAddress((void**)&v_p,    g_v);
    cudaGetSymbolAddress((void**)&att0_p, g_att0);
    cudaGetSymbolAddress((void**)&att2_p, g_att2);
    cudaGetSymbolAddress((void**)&wcl_p,  g_wcl);
    cudaGetSymbolAddress((void**)&y_p,    g_y);

    const long long sTT = (long long)TT * TT;          // 1 M
    const long long sBTC = (long long)TT * CC;         // 786432

    // 1) Wcl = Wc @ Wl   (NN, 1024^3)
    gemm_k<128,128,16,8,8,false,false><<<dim3(8,8,1),256>>>(
        Wc, Wl, nullptr, wcl_p,
        TT, TT, TT, TT, TT, TT,
        0,0, 0,0, 0,0, 1, 1.0f);

    // 2) v = x @ Wv^T + bv   (NT, [8192,768,768])
    gemm_k<128,128,16,8,8,true,false><<<dim3(CC/128, (BB*TT)/128, 1),256>>>(
        x, Wv, bv, v_p,
        BB*TT, CC, CC, CC, CC, CC,
        0,0, 0,0, 0,0, 1, 1.0f);

    // 3) att0 = (vh @ vh^T) / 8   per (b,h)   (NT batched, K=64)
    gemm_k<128,128,16,8,8,true,false><<<dim3(8,8,BB*NHH),256>>>(
        v_p, v_p, nullptr, att0_p,
        TT, TT, HDD, CC, CC, TT,
        sBTC, HDD, sBTC, HDD, (long long)NHH*sTT, sTT,
        NHH, 0.125f);

    // 4) att2 = att0 @ Wcl^T + bc   (NT batched, causal tile skip)
    gemm_k<128,128,16,8,8,true,true><<<dim3(8,8,BB*NHH),256>>>(
        att0_p, wcl_p, bc, att2_p,
        TT, TT, TT, TT, TT, TT,
        (long long)NHH*sTT, sTT, 0,0, (long long)NHH*sTT, sTT,
        NHH, 1.0f);

    // 5) causal softmax in-place on att2
    softmax_causal_k<<<dim3(TT, BB*NHH), 256>>>(att2_p);

    // 6) y = att2 @ vh   (NN batched, N=64) -> write directly to [B,T,C] layout
    gemm_k<128,64,16,8,4,false,false><<<dim3(1,8,BB*NHH),256>>>(
        att2_p, v_p, nullptr, y_p,
        TT, HDD, TT, TT, CC, CC,
        (long long)NHH*sTT, sTT, sBTC, HDD, sBTC, HDD,
        NHH, 1.0f);

    // 7) out = y @ Wp^T + bp   (NT, [8192,768,768])
    gemm_k<128,128,16,8,8,true,false><<<dim3(CC/128, (BB*TT)/128, 1),256>>>(
        y_p, Wp, bp, out,
        BB*TT, CC, CC, CC, CC, CC,
        0,0, 0,0, 0,0, 1, 1.0f);
}

// round 4
// speedup vs baseline: 1.5420x; 1.5420x over previous
#include <cuda_runtime.h>
#include <math.h>
#include <stdint.h>

// Problem constants
#define BB 8
#define TT 1024
#define CC 768
#define NHH 12
#define HDD 64

// Scratch (static __device__ arrays: no allocation allowed)
__device__ float g_v  [BB * TT * CC];
__device__ float g_att0[(long long)BB * NHH * TT * TT];
__device__ float g_att2[(long long)BB * NHH * TT * TT];
__device__ float g_wcl[TT * TT];
__device__ float g_y  [BB * TT * CC];

// ===========================================================================
// tf32 helpers (base sm_80+ ISA — no tcgen05; harness compiles compute_103)
// ===========================================================================
__device__ __forceinline__ uint32_t f2tf32(float x) {
    uint32_t u;
    asm("cvt.rna.tf32.f32 %0, %1;" : "=r"(u) : "f"(x));
    return u;
}

__device__ __forceinline__ void mma_tf32_16x8x8(
    float* d, const float4& a, const float2& b)
{
    asm volatile(
        "mma.sync.aligned.m16n8k8.row.col.f32.tf32.tf32.f32 "
        "{%0,%1,%2,%3}, {%4,%5,%6,%7}, {%8,%9}, {%0,%1,%2,%3};"
        : "+f"(d[0]), "+f"(d[1]), "+f"(d[2]), "+f"(d[3])
        : "r"(__float_as_uint(a.x)), "r"(__float_as_uint(a.y)),
          "r"(__float_as_uint(a.z)), "r"(__float_as_uint(a.w)),
          "r"(__float_as_uint(b.x)), "r"(__float_as_uint(b.y)));
}

// ===========================================================================
// Step 4: att2[z] = att0[z] @ Wcl^T + bc  (tf32 mma.sync, causal tile skip)
//
// CTA: 128x128 tile, 256 thr = 8 warps (2 m-warps x 4 n-warps), warp = 64x32.
// BK = 32 (4 k-atoms of 8). Smem holds A/B tiles pre-converted to tf32 and
// scattered into mma fragment layout:
//   sA[ka][ma][lane][r]  (r = a0..a3)  -> one LDS.128 per (ka, ma)
//   sB[ka][na][lane][r]  (r = b0..b1)  -> one LDS.64  per (ka, na)
// Fragment maps (PTX m16n8k8 tf32, row.col):
//   A elem (mr, kc): lane = (mr&7)*4 + (kc&3), r = (kc>>2)*2 + (mr>>3)
//   B elem (kc, nr): lane = nr*4 + (kc&3),     r = kc>>2
// ===========================================================================
__global__ void __launch_bounds__(256)
att_mix_mma_kernel(const float* __restrict__ att0, const float* __restrict__ wcl,
                   const float* __restrict__ bc, float* __restrict__ att2)
{
    const int nt = blockIdx.x, mt = blockIdx.y;
    if (nt > mt) return;  // tile fully above diagonal: softmax never reads it
    const long long z = blockIdx.z;
    const float* Az = att0 + z * (long long)(TT * TT) + (long long)mt * 128 * TT;
    const float* Bz = wcl + (long long)nt * 128 * TT;
    float* Cz = att2 + z * (long long)(TT * TT);

    __shared__ float sA[4][8][32][4];   // 16 KB
    __shared__ float sB[4][16][32][2];  // 16 KB

    const int tid = threadIdx.x;
    const int lane = tid & 31;
    const int w = tid >> 5;
    const int wm = w >> 2;        // 0..1
    const int wn = w & 3;         // 0..3
    const int ma_base = wm * 4;   // m-atom 16 rows; warp covers 4
    const int na_base = wn * 4;   // n-atom 8 cols;  warp covers 4

    float acc[4][4][4];
#pragma unroll
    for (int i = 0; i < 4; i++)
#pragma unroll
        for (int j = 0; j < 4; j++)
#pragma unroll
            for (int r = 0; r < 4; r++) acc[i][j][r] = 0.f;

    for (int k0 = 0; k0 < TT; k0 += 32) {
        // ---- A tile: 128 rows x 32 cols, 1024 float4, 4 per thread ----
#pragma unroll
        for (int i = 0; i < 4; i++) {
            int v = tid + i * 256;
            int row = v >> 3;            // 0..127
            int c4  = v & 7;             // float4 index in row
            int kcol = c4 * 4;
            int ka = kcol >> 3;
            int colhalf = c4 & 1;        // (kcol%8) >= 4
            int maA = row >> 4;
            int mr = row & 15;
            int r = colhalf * 2 + (mr >> 3);
            int laneA = (mr & 7) * 4;
            float4 t = *reinterpret_cast<const float4*>(&Az[(long long)row * TT + k0 + kcol]);
            sA[ka][maA][laneA + 0][r] = __uint_as_float(f2tf32(t.x));
            sA[ka][maA][laneA + 1][r] = __uint_as_float(f2tf32(t.y));
            sA[ka][maA][laneA + 2][r] = __uint_as_float(f2tf32(t.z));
            sA[ka][maA][laneA + 3][r] = __uint_as_float(f2tf32(t.w));
        }
        // ---- B tile: 128 n-rows x 32 k-cols (Wcl rows are n) ----
#pragma unroll
        for (int i = 0; i < 4; i++) {
            int v = tid + i * 256;
            int n  = v >> 3;             // 0..127
            int c4 = v & 7;
            int kcol = c4 * 4;
            int ka = kcol >> 3;
            int r  = c4 & 1;             // kc >> 2
            int naB = n >> 3;
            int nr = n & 7;
            int laneB = nr * 4;
            float4 t = *reinterpret_cast<const float4*>(&Bz[(long long)n * TT + k0 + kcol]);
            sB[ka][naB][laneB + 0][r] = __uint_as_float(f2tf32(t.x));
            sB[ka][naB][laneB + 1][r] = __uint_as_float(f2tf32(t.y));
            sB[ka][naB][laneB + 2][r] = __uint_as_float(f2tf32(t.z));
            sB[ka][naB][laneB + 3][r] = __uint_as_float(f2tf32(t.w));
        }
        __syncthreads();

        // ---- compute: 4 k-atoms x (4 m-atoms x 4 n-atoms) mma ----
#pragma unroll
        for (int ka = 0; ka < 4; ka++) {
            float4 aF[4];
            float2 bF[4];
#pragma unroll
            for (int i = 0; i < 4; i++)
                aF[i] = *reinterpret_cast<const float4*>(&sA[ka][ma_base + i][lane][0]);
#pragma unroll
            for (int j = 0; j < 4; j++)
                bF[j] = *reinterpret_cast<const float2*>(&sB[ka][na_base + j][lane][0]);
#pragma unroll
            for (int i = 0; i < 4; i++)
#pragma unroll
                for (int j = 0; j < 4; j++)
                    mma_tf32_16x8x8(acc[i][j], aF[i], bF[j]);
        }
        __syncthreads();
    }

    // ---- epilogue: bias add, float2 stores ----
    const int m_base = mt * 128 + wm * 64;
    const int n_base = nt * 128 + wn * 32;
#pragma unroll
    for (int i = 0; i < 4; i++) {
        int row0 = m_base + i * 16 + (lane >> 2);
#pragma unroll
        for (int j = 0; j < 4; j++) {
            int col = n_base + j * 8 + (lane & 3) * 2;
            float b0 = bc[col], b1 = bc[col + 1];
            float2 t0 = make_float2(acc[i][j][0] + b0, acc[i][j][1] + b1);
            float2 t1 = make_float2(acc[i][j][2] + b0, acc[i][j][3] + b1);
            *reinterpret_cast<float2*>(&Cz[(long long)row0 * TT + col]) = t0;
            *reinterpret_cast<float2*>(&Cz[(long long)(row0 + 8) * TT + col]) = t1;
        }
    }
}

// ===========================================================================
// Generic batched tiled FP32 GEMM (unchanged)
// ===========================================================================
template<int BM, int BN, int BK, int TM, int TN, bool TB, bool CAUSAL_SKIP>
__global__ void __launch_bounds__((BM/TM)*(BN/TN))
gemm_k(const float* __restrict__ A, const float* __restrict__ Bm,
       const float* __restrict__ bias, float* __restrict__ Cm,
       int M, int N, int K, int lda, int ldb, int ldc,
       long long sAb, long long sAh, long long sBb, long long sBh,
       long long sCb, long long sCh, int batchH, float alpha)
{
    constexpr int THREADS = (BM/TM)*(BN/TN);
    const int z = blockIdx.z;
    const int b = z / batchH, h = z % batchH;
    const float* Ab = A  + b * sAb + h * sAh;
    const float* Bb = Bm + b * sBb + h * sBh;
    float*       Cb = Cm + b * sCb + h * sCh;

    const int m0 = blockIdx.y * BM;
    const int n0 = blockIdx.x * BN;
    if (CAUSAL_SKIP && n0 > m0 + BM - 1) return;

    __shared__ float As[BK][BM];
    __shared__ float Bs[BK][BN];

    const int tid = threadIdx.x;
    float acc[TM][TN];
#pragma unroll
    for (int i = 0; i < TM; i++)
#pragma unroll
        for (int j = 0; j < TN; j++) acc[i][j] = 0.f;

    constexpr int A_VECS = BM * BK / 4;
    constexpr int A_PER  = A_VECS / THREADS;
    constexpr int B_VECS = BN * BK / 4;
    constexpr int B_PER  = B_VECS / THREADS;
    static_assert(A_PER * THREADS == A_VECS, "A tiling");
    static_assert(B_PER * THREADS == B_VECS, "B tiling");

    const int tr = (tid / (BN/TN)) * TM;
    const int tc = (tid % (BN/TN)) * TN;

    for (int k0 = 0; k0 < K; k0 += BK) {
#pragma unroll
        for (int i = 0; i < A_PER; i++) {
            int v   = tid + i * THREADS;
            int row = v / (BK/4);
            int kc  = (v % (BK/4)) * 4;
            float4 t = *reinterpret_cast<const float4*>(
                &Ab[(long long)(m0 + row) * lda + k0 + kc]);
            As[kc+0][row] = t.x; As[kc+1][row] = t.y;
            As[kc+2][row] = t.z; As[kc+3][row] = t.w;
        }
        if constexpr (TB) {
#pragma unroll
            for (int i = 0; i < B_PER; i++) {
                int v   = tid + i * THREADS;
                int row = v / (BK/4);
                int kc  = (v % (BK/4)) * 4;
                float4 t = *reinterpret_cast<const float4*>(
                    &Bb[(long long)(n0 + row) * ldb + k0 + kc]);
                Bs[kc+0][row] = t.x; Bs[kc+1][row] = t.y;
                Bs[kc+2][row] = t.z; Bs[kc+3][row] = t.w;
            }
        } else {
#pragma unroll
            for (int i = 0; i < B_PER; i++) {
                int v    = tid + i * THREADS;
                int krow = v / (BN/4);
                int nc   = (v % (BN/4)) * 4;
                float4 t = *reinterpret_cast<const float4*>(
                    &Bb[(long long)(k0 + krow) * ldb + n0 + nc]);
                *reinterpret_cast<float4*>(&Bs[krow][nc]) = t;
            }
        }
        __syncthreads();

#pragma unroll
        for (int kk = 0; kk < BK; kk++) {
            float ar[TM], br[TN];
#pragma unroll
            for (int i = 0; i < TM; i++) ar[i] = As[kk][tr + i];
#pragma unroll
            for (int j = 0; j < TN; j++) br[j] = Bs[kk][tc + j];
#pragma unroll
            for (int i = 0; i < TM; i++)
#pragma unroll
                for (int j = 0; j < TN; j++)
                    acc[i][j] += ar[i] * br[j];
        }
        __syncthreads();
    }

#pragma unroll
    for (int i = 0; i < TM; i++) {
        long long crow = (long long)(m0 + tr + i) * ldc + n0 + tc;
#pragma unroll
        for (int j = 0; j < TN; j += 4) {
            float4 t;
            t.x = acc[i][j+0] * alpha + (bias ? bias[n0 + tc + j + 0] : 0.f);
            t.y = acc[i][j+1] * alpha + (bias ? bias[n0 + tc + j + 1] : 0.f);
            t.z = acc[i][j+2] * alpha + (bias ? bias[n0 + tc + j + 2] : 0.f);
            t.w = acc[i][j+3] * alpha + (bias ? bias[n0 + tc + j + 3] : 0.f);
            *reinterpret_cast<float4*>(&Cb[crow + j]) = t;
        }
    }
}

// ---------------------------------------------------------------------------
// Causal softmax (unchanged)
// ---------------------------------------------------------------------------
__device__ __forceinline__ float warp_max(float v) {
#pragma unroll
    for (int o = 16; o; o >>= 1) v = fmaxf(v, __shfl_xor_sync(0xffffffffu, v, o));
    return v;
}
__device__ __forceinline__ float warp_sum(float v) {
#pragma unroll
    for (int o = 16; o; o >>= 1) v += __shfl_xor_sync(0xffffffffu, v, o);
    return v;
}

__global__ void softmax_causal_k(float* __restrict__ att)
{
    const long long z = blockIdx.y;
    const int q = blockIdx.x;
    float* row = att + (z * TT + q) * (long long)TT;
    const int L = q + 1;
    const int tid = threadIdx.x;
    __shared__ float red[8];

    float m = -INFINITY;
    for (int j = tid; j < L; j += blockDim.x) m = fmaxf(m, row[j]);
    m = warp_max(m);
    if ((tid & 31) == 0) red[tid >> 5] = m;
    __syncthreads();
    if (tid < 32) {
        float v = (tid < 8) ? red[tid] : -INFINITY;
        v = warp_max(v);
        if (tid == 0) red[0] = v;
    }
    __syncthreads();
    const float mg = red[0];
    __syncthreads();

    float s = 0.f;
    for (int j = tid; j < L; j += blockDim.x) s += __expf(row[j] - mg);
    s = warp_sum(s);
    if ((tid & 31) == 0) red[tid >> 5] = s;
    __syncthreads();
    if (tid < 32) {
        float v = (tid < 8) ? red[tid] : 0.f;
        v = warp_sum(v);
        if (tid == 0) red[0] = v;
    }
    __syncthreads();
    const float inv = 1.f / red[0];

    for (int j = tid; j < TT; j += blockDim.x)
        row[j] = (j < L) ? __expf(row[j] - mg) * inv : 0.f;
}

// ---------------------------------------------------------------------------
extern "C" void kernel_launch(void* const* d_in, const int* in_sizes, int n_in,
                              void* d_out, int out_size)
{
    const float* x  = (const float*)d_in[0];
    const float* Wv = (const float*)d_in[1];
    const float* bv = (const float*)d_in[2];
    const float* Wl = (const float*)d_in[3];
    const float* Wc = (const float*)d_in[4];
    const float* bc = (const float*)d_in[5];
    const float* Wp = (const float*)d_in[6];
    const float* bp = (const float*)d_in[7];
    float* out = (float*)d_out;

    float *v_p, *att0_p, *att2_p, *wcl_p, *y_p;
    cudaGetSymbolAddress((void**)&v_p,    g_v);
    cudaGetSymbolAddress((void**)&att0_p, g_att0);
    cudaGetSymbolAddress((void**)&att2_p, g_att2);
    cudaGetSymbolAddress((void**)&wcl_p,  g_wcl);
    cudaGetSymbolAddress((void**)&y_p,    g_y);

    const long long sTT = (long long)TT * TT;
    const long long sBTC = (long long)TT * CC;

    // 1) Wcl = Wc @ Wl
    gemm_k<128,128,16,8,8,false,false><<<dim3(8,8,1),256>>>(
        Wc, Wl, nullptr, wcl_p,
        TT, TT, TT, TT, TT, TT,
        0,0, 0,0, 0,0, 1, 1.0f);

    // 2) v = x @ Wv^T + bv
    gemm_k<128,128,16,8,8,true,false><<<dim3(CC/128, (BB*TT)/128, 1),256>>>(
        x, Wv, bv, v_p,
        BB*TT, CC, CC, CC, CC, CC,
        0,0, 0,0, 0,0, 1, 1.0f);

    // 3) att0 = (vh @ vh^T) / 8
    gemm_k<128,128,16,8,8,true,false><<<dim3(8,8,BB*NHH),256>>>(
        v_p, v_p, nullptr, att0_p,
        TT, TT, HDD, CC, CC, TT,
        sBTC, HDD, sBTC, HDD, (long long)NHH*sTT, sTT,
        NHH, 0.125f);

    // 4) att2 = att0 @ Wcl^T + bc — tf32 mma.sync, causal tile skip
    att_mix_mma_kernel<<<dim3(8, 8, BB*NHH), 256>>>(att0_p, wcl_p, bc, att2_p);

    // 5) causal softmax in-place on att2
    softmax_causal_k<<<dim3(TT, BB*NHH), 256>>>(att2_p);

    // 6) y = att2 @ vh
    gemm_k<128,64,16,8,4,false,false><<<dim3(1,8,BB*NHH),256>>>(
        att2_p, v_p, nullptr, y_p,
        TT, HDD, TT, TT, CC, CC,
        (long long)NHH*sTT, sTT, sBTC, HDD, sBTC, HDD,
        NHH, 1.0f);

    // 7) out = y @ Wp^T + bp
    gemm_k<128,128,16,8,8,true,false><<<dim3(CC/128, (BB*TT)/128, 1),256>>>(
        y_p, Wp, bp, out,
        BB*TT, CC, CC, CC, CC, CC,
        0,0, 0,0, 0,0, 1, 1.0f);
}

// round 5
// speedup vs baseline: 1.9098x; 1.2385x over previous
#include <cuda_runtime.h>
#include <math.h>
#include <stdint.h>

// Problem constants
#define BB 8
#define TT 1024
#define CC 768
#define NHH 12
#define HDD 64

// Scratch (static __device__ arrays: no allocation allowed)
__device__ float g_v  [BB * TT * CC];
__device__ float g_att0[(long long)BB * NHH * TT * TT];
__device__ float g_att2[(long long)BB * NHH * TT * TT];
__device__ float g_wcl[TT * TT];
__device__ float g_y  [BB * TT * CC];

// ===========================================================================
// tf32 helpers (base sm_80+ ISA — harness compiles compute_103, no tcgen05)
// ===========================================================================
__device__ __forceinline__ float f2tf32f(float x) {
    uint32_t u;
    asm("cvt.rna.tf32.f32 %0, %1;" : "=r"(u) : "f"(x));
    return __uint_as_float(u);
}

__device__ __forceinline__ void mma_tf32_16x8x8(
    float* d, const float4& a, const float2& b)
{
    asm volatile(
        "mma.sync.aligned.m16n8k8.row.col.f32.tf32.tf32.f32 "
        "{%0,%1,%2,%3}, {%4,%5,%6,%7}, {%8,%9}, {%0,%1,%2,%3};"
        : "+f"(d[0]), "+f"(d[1]), "+f"(d[2]), "+f"(d[3])
        : "r"(__float_as_uint(a.x)), "r"(__float_as_uint(a.y)),
          "r"(__float_as_uint(a.z)), "r"(__float_as_uint(a.w)),
          "r"(__float_as_uint(b.x)), "r"(__float_as_uint(b.y)));
}

// ===========================================================================
// Generic batched tf32 mma.sync GEMM.
//   TB=true : C = alpha * A @ B^T + bias   (B: [N,K] ldb)
//   TB=false: C = alpha * A @ B   + bias   (B: [K,N] ldb)
// BM=128, BK=32, 256 threads = 8 warps in WM x WN grid.
// SKIP_OUT: skip output tiles fully above diagonal (causal, square tiles).
// SKIP_K:   K loop limited to (mt+1)*BM (A rows zero beyond diagonal band).
// Smem tiles stored in mma fragment layout (scatter on store, vector LDS on read):
//   A elem (mr, kc): lane=(mr&7)*4+(kc&3), r=(kc>>2)*2+(mr>>3)
//   B elem (kc, nr): lane=(nr&7)*4+(kc&3), r=kc>>2
// ===========================================================================
template<int BN, int WM, int WN, bool TB, bool SKIP_OUT, bool SKIP_K>
__global__ void __launch_bounds__(256)
gemm_mma_k(const float* __restrict__ A, const float* __restrict__ Bm,
           const float* __restrict__ bias, float* __restrict__ Cm,
           int K, int lda, int ldb, int ldc,
           long long sAb, long long sAh, long long sBb, long long sBh,
           long long sCb, long long sCh, int batchH, float alpha)
{
    constexpr int BM = 128, BK = 32;
    constexpr int MA = BM / WM / 16;  // m-atoms per warp
    constexpr int NA = BN / WN / 8;   // n-atoms per warp
    static_assert(WM * WN == 8, "8 warps");

    const int nt = blockIdx.x, mt = blockIdx.y;
    if (SKIP_OUT && nt > mt) return;
    const int z = blockIdx.z;
    const int b = z / batchH, h = z % batchH;
    const float* Az = A + b * sAb + h * sAh + (long long)mt * BM * lda;
    const float* Bz = Bm + b * sBb + h * sBh
                    + (TB ? (long long)nt * BN * ldb : (long long)nt * BN);
    float* Cz = Cm + b * sCb + h * sCh;

    __shared__ float sA[4][8][32][4];        // 16 KB
    __shared__ float sB[4][BN / 8][32][2];   // 16 or 8 KB

    const int tid = threadIdx.x, lane = tid & 31, w = tid >> 5;
    const int wm = w / WN, wn = w % WN;

    float acc[MA][NA][4];
#pragma unroll
    for (int i = 0; i < MA; i++)
#pragma unroll
        for (int j = 0; j < NA; j++)
#pragma unroll
            for (int r = 0; r < 4; r++) acc[i][j][r] = 0.f;

    const int kmax = SKIP_K ? (mt + 1) * BM : K;

    for (int k0 = 0; k0 < kmax; k0 += BK) {
        // ---- A tile: 128 rows x 32 k ----
#pragma unroll
        for (int i = 0; i < 4; i++) {
            int v = tid + i * 256;
            int row = v >> 3, c4 = v & 7;
            int ka = c4 >> 1;
            int r = (c4 & 1) * 2 + ((row >> 3) & 1);
            int ma = row >> 4, laneA = (row & 7) * 4;
            float4 t = *reinterpret_cast<const float4*>(
                &Az[(long long)row * lda + k0 + c4 * 4]);
            sA[ka][ma][laneA + 0][r] = f2tf32f(t.x);
            sA[ka][ma][laneA + 1][r] = f2tf32f(t.y);
            sA[ka][ma][laneA + 2][r] = f2tf32f(t.z);
            sA[ka][ma][laneA + 3][r] = f2tf32f(t.w);
        }
        // ---- B tile ----
        if constexpr (TB) {
#pragma unroll
            for (int i = 0; i < BN / 32; i++) {
                int v = tid + i * 256;
                int n = v >> 3, c4 = v & 7;
                int ka = c4 >> 1, r = c4 & 1;
                int na = n >> 3, laneB = (n & 7) * 4;
                float4 t = *reinterpret_cast<const float4*>(
                    &Bz[(long long)n * ldb + k0 + c4 * 4]);
                sB[ka][na][laneB + 0][r] = f2tf32f(t.x);
                sB[ka][na][laneB + 1][r] = f2tf32f(t.y);
                sB[ka][na][laneB + 2][r] = f2tf32f(t.z);
                sB[ka][na][laneB + 3][r] = f2tf32f(t.w);
            }
        } else {
#pragma unroll
            for (int i = 0; i < BN / 32; i++) {
                int v = tid + i * 256;
                int krow = v / (BN / 4);
                int nc = (v % (BN / 4)) * 4;
                int ka = krow >> 3, kc = krow & 7;
                int r = kc >> 2, lc = kc & 3;
                int na = nc >> 3, nb = nc & 7;
                float4 t = *reinterpret_cast<const float4*>(
                    &Bz[(long long)(k0 + krow) * ldb + nc]);
                sB[ka][na][(nb + 0) * 4 + lc][r] = f2tf32f(t.x);
                sB[ka][na][(nb + 1) * 4 + lc][r] = f2tf32f(t.y);
                sB[ka][na][(nb + 2) * 4 + lc][r] = f2tf32f(t.z);
                sB[ka][na][(nb + 3) * 4 + lc][r] = f2tf32f(t.w);
            }
        }
        __syncthreads();

#pragma unroll
        for (int ka = 0; ka < 4; ka++) {
            float4 aF[MA];
            float2 bF[NA];
#pragma unroll
            for (int i = 0; i < MA; i++)
                aF[i] = *reinterpret_cast<const float4*>(&sA[ka][wm * MA + i][lane][0]);
#pragma unroll
            for (int j = 0; j < NA; j++)
                bF[j] = *reinterpret_cast<const float2*>(&sB[ka][wn * NA + j][lane][0]);
#pragma unroll
            for (int i = 0; i < MA; i++)
#pragma unroll
                for (int j = 0; j < NA; j++)
                    mma_tf32_16x8x8(acc[i][j], aF[i], bF[j]);
        }
        __syncthreads();
    }

    // ---- epilogue ----
    const int m_base = mt * BM + wm * (MA * 16);
    const int n_base = nt * BN + wn * (NA * 8);
#pragma unroll
    for (int i = 0; i < MA; i++) {
        int row0 = m_base + i * 16 + (lane >> 2);
#pragma unroll
        for (int j = 0; j < NA; j++) {
            int col = n_base + j * 8 + (lane & 3) * 2;
            float b0 = bias ? bias[col] : 0.f;
            float b1 = bias ? bias[col + 1] : 0.f;
            float2 t0 = make_float2(acc[i][j][0] * alpha + b0,
                                    acc[i][j][1] * alpha + b1);
            float2 t1 = make_float2(acc[i][j][2] * alpha + b0,
                                    acc[i][j][3] * alpha + b1);
            *reinterpret_cast<float2*>(&Cz[(long long)row0 * ldc + col]) = t0;
            *reinterpret_cast<float2*>(&Cz[(long long)(row0 + 8) * ldc + col]) = t1;
        }
    }
}

// ===========================================================================
// Generic batched tiled FP32 GEMM (for steps 1 & 2 — precision hedge)
// ===========================================================================
template<int BM, int BN, int BK, int TM, int TN, bool TB>
__global__ void __launch_bounds__((BM/TM)*(BN/TN))
gemm_k(const float* __restrict__ A, const float* __restrict__ Bm,
       const float* __restrict__ bias, float* __restrict__ Cm,
       int M, int N, int K, int lda, int ldb, int ldc, float alpha)
{
    constexpr int THREADS = (BM/TM)*(BN/TN);
    const int m0 = blockIdx.y * BM;
    const int n0 = blockIdx.x * BN;

    __shared__ float As[BK][BM];
    __shared__ float Bs[BK][BN];

    const int tid = threadIdx.x;
    float acc[TM][TN];
#pragma unroll
    for (int i = 0; i < TM; i++)
#pragma unroll
        for (int j = 0; j < TN; j++) acc[i][j] = 0.f;

    constexpr int A_PER = BM * BK / 4 / THREADS;
    constexpr int B_PER = BN * BK / 4 / THREADS;

    const int tr = (tid / (BN/TN)) * TM;
    const int tc = (tid % (BN/TN)) * TN;

    for (int k0 = 0; k0 < K; k0 += BK) {
#pragma unroll
        for (int i = 0; i < A_PER; i++) {
            int v   = tid + i * THREADS;
            int row = v / (BK/4);
            int kc  = (v % (BK/4)) * 4;
            float4 t = *reinterpret_cast<const float4*>(
                &A[(long long)(m0 + row) * lda + k0 + kc]);
            As[kc+0][row] = t.x; As[kc+1][row] = t.y;
            As[kc+2][row] = t.z; As[kc+3][row] = t.w;
        }
        if constexpr (TB) {
#pragma unroll
            for (int i = 0; i < B_PER; i++) {
                int v   = tid + i * THREADS;
                int row = v / (BK/4);
                int kc  = (v % (BK/4)) * 4;
                float4 t = *reinterpret_cast<const float4*>(
                    &Bm[(long long)(n0 + row) * ldb + k0 + kc]);
                Bs[kc+0][row] = t.x; Bs[kc+1][row] = t.y;
                Bs[kc+2][row] = t.z; Bs[kc+3][row] = t.w;
            }
        } else {
#pragma unroll
            for (int i = 0; i < B_PER; i++) {
                int v    = tid + i * THREADS;
                int krow = v / (BN/4);
                int nc   = (v % (BN/4)) * 4;
                float4 t = *reinterpret_cast<const float4*>(
                    &Bm[(long long)(k0 + krow) * ldb + n0 + nc]);
                *reinterpret_cast<float4*>(&Bs[krow][nc]) = t;
            }
        }
        __syncthreads();

#pragma unroll
        for (int kk = 0; kk < BK; kk++) {
            float ar[TM], br[TN];
#pragma unroll
            for (int i = 0; i < TM; i++) ar[i] = As[kk][tr + i];
#pragma unroll
            for (int j = 0; j < TN; j++) br[j] = Bs[kk][tc + j];
#pragma unroll
            for (int i = 0; i < TM; i++)
#pragma unroll
                for (int j = 0; j < TN; j++)
                    acc[i][j] += ar[i] * br[j];
        }
        __syncthreads();
    }

#pragma unroll
    for (int i = 0; i < TM; i++) {
        long long crow = (long long)(m0 + tr + i) * ldc + n0 + tc;
#pragma unroll
        for (int j = 0; j < TN; j += 4) {
            float4 t;
            t.x = acc[i][j+0] * alpha + (bias ? bias[n0 + tc + j + 0] : 0.f);
            t.y = acc[i][j+1] * alpha + (bias ? bias[n0 + tc + j + 1] : 0.f);
            t.z = acc[i][j+2] * alpha + (bias ? bias[n0 + tc + j + 2] : 0.f);
            t.w = acc[i][j+3] * alpha + (bias ? bias[n0 + tc + j + 3] : 0.f);
            *reinterpret_cast<float4*>(&Cm[crow + j]) = t;
        }
    }
}

// ---------------------------------------------------------------------------
// Causal softmax with smem row cache.
// Writes only columns < ((q>>7)+1)*128: step 6's K-skip never reads beyond
// the diagonal 128-band, and zeros inside the band come from the mask.
// ---------------------------------------------------------------------------
__device__ __forceinline__ float warp_max(float v) {
#pragma unroll
    for (int o = 16; o; o >>= 1) v = fmaxf(v, __shfl_xor_sync(0xffffffffu, v, o));
    return v;
}
__device__ __forceinline__ float warp_sum(float v) {
#pragma unroll
    for (int o = 16; o; o >>= 1) v += __shfl_xor_sync(0xffffffffu, v, o);
    return v;
}

__global__ void __launch_bounds__(256)
softmax_causal_k(float* __restrict__ att)
{
    const long long z = blockIdx.y;
    const int q = blockIdx.x;
    float* row = att + (z * TT + q) * (long long)TT;
    const int L = q + 1;
    const int tid = threadIdx.x;
    __shared__ float srow[TT];
    __shared__ float red[8];

    float m = -INFINITY;
    for (int j = tid; j < L; j += 256) {
        float v = row[j];
        srow[j] = v;
        m = fmaxf(m, v);
    }
    m = warp_max(m);
    if ((tid & 31) == 0) red[tid >> 5] = m;
    __syncthreads();
    if (tid < 32) {
        float v = (tid < 8) ? red[tid] : -INFINITY;
        v = warp_max(v);
        if (tid == 0) red[0] = v;
    }
    __syncthreads();
    const float mg = red[0];
    __syncthreads();

    float s = 0.f;
    for (int j = tid; j < L; j += 256) {
        float e = __expf(srow[j] - mg);
        srow[j] = e;             // each thread touches only its own indices
        s += e;
    }
    s = warp_sum(s);
    if ((tid & 31) == 0) red[tid >> 5] = s;
    __syncthreads();
    if (tid < 32) {
        float v = (tid < 8) ? red[tid] : 0.f;
        v = warp_sum(v);
        if (tid == 0) red[0] = v;
    }
    __syncthreads();
    const float inv = 1.f / red[0];

    const int wlimit = ((q >> 7) + 1) << 7;   // end of diagonal 128-band
    for (int j = tid; j < wlimit; j += 256)
        row[j] = (j < L) ? srow[j] * inv : 0.f;
}

// ---------------------------------------------------------------------------
extern "C" void kernel_launch(void* const* d_in, const int* in_sizes, int n_in,
                              void* d_out, int out_size)
{
    const float* x  = (const float*)d_in[0];
    const float* Wv = (const float*)d_in[1];
    const float* bv = (const float*)d_in[2];
    const float* Wl = (const float*)d_in[3];
    const float* Wc = (const float*)d_in[4];
    const float* bc = (const float*)d_in[5];
    const float* Wp = (const float*)d_in[6];
    const float* bp = (const float*)d_in[7];
    float* out = (float*)d_out;

    float *v_p, *att0_p, *att2_p, *wcl_p, *y_p;
    cudaGetSymbolAddress((void**)&v_p,    g_v);
    cudaGetSymbolAddress((void**)&att0_p, g_att0);
    cudaGetSymbolAddress((void**)&att2_p, g_att2);
    cudaGetSymbolAddress((void**)&wcl_p,  g_wcl);
    cudaGetSymbolAddress((void**)&y_p,    g_y);

    const long long sTT  = (long long)TT * TT;
    const long long sBTC = (long long)TT * CC;

    // 1) Wcl = Wc @ Wl   (fp32 — feeds the dominant tf32 GEMM's B operand)
    gemm_k<128,128,16,8,8,false><<<dim3(8,8,1),256>>>(
        Wc, Wl, nullptr, wcl_p, TT, TT, TT, TT, TT, TT, 1.0f);

    // 2) v = x @ Wv^T + bv   (fp32 — v feeds q, k, v; keep exact)
    gemm_k<128,128,16,8,8,true><<<dim3(CC/128, (BB*TT)/128, 1),256>>>(
        x, Wv, bv, v_p, BB*TT, CC, CC, CC, CC, CC, 1.0f);

    // 3) att0 = (vh @ vh^T) / 8   (tf32 NT batched, K=64)
    gemm_mma_k<128,2,4,true,false,false><<<dim3(8,8,BB*NHH),256>>>(
        v_p, v_p, nullptr, att0_p,
        HDD, CC, CC, TT,
        sBTC, HDD, sBTC, HDD, (long long)NHH*sTT, sTT,
        NHH, 0.125f);

    // 4) att2 = att0 @ Wcl^T + bc   (tf32 NT batched, causal tile skip)
    gemm_mma_k<128,2,4,true,true,false><<<dim3(8,8,BB*NHH),256>>>(
        att0_p, wcl_p, bc, att2_p,
        TT, TT, TT, TT,
        (long long)NHH*sTT, sTT, 0,0, (long long)NHH*sTT, sTT,
        NHH, 1.0f);

    // 5) causal softmax in-place on att2
    softmax_causal_k<<<dim3(TT, BB*NHH), 256>>>(att2_p);

    // 6) y = att2 @ vh   (tf32 NN batched, N=64, causal K-skip)
    gemm_mma_k<64,4,2,false,false,true><<<dim3(1,8,BB*NHH),256>>>(
        att2_p, v_p, nullptr, y_p,
        TT, TT, CC, CC,
        (long long)NHH*sTT, sTT, sBTC, HDD, sBTC, HDD,
        NHH, 1.0f);

    // 7) out = y @ Wp^T + bp   (tf32 NT)
    gemm_mma_k<128,2,4,true,false,false><<<dim3(CC/128, (BB*TT)/128, 1),256>>>(
        y_p, Wp, bp, out,
        CC, CC, CC, CC,
        0,0, 0,0, 0,0, 1, 1.0f);
}

// round 7
// speedup vs baseline: 3.1302x; 1.6391x over previous
#include <cuda_runtime.h>
#include <math.h>
#include <stdint.h>

// Problem constants
#define BB 8
#define TT 1024
#define CC 768
#define NHH 12
#define HDD 64

// Scratch (static __device__ arrays: no allocation allowed)
__device__ float g_v  [BB * TT * CC];                  // value projection [B,T,C]
__device__ float g_u  [BB * NHH * TT * HDD];           // u = Wcl @ vh  [z,T,64]
__device__ float g_att2[(long long)BB * NHH * TT * TT]; // logits / probs
__device__ float g_wcl[TT * TT];                       // Wc @ Wl
__device__ float g_y  [BB * TT * CC];                  // attention output [B,T,C]

// ===========================================================================
// tf32 helpers (base sm_80+ ISA — harness compiles compute_103, no tcgen05)
// ===========================================================================
__device__ __forceinline__ float f2tf32f(float x) {
    uint32_t u;
    asm("cvt.rna.tf32.f32 %0, %1;" : "=r"(u) : "f"(x));
    return __uint_as_float(u);
}

__device__ __forceinline__ void mma_tf32_16x8x8(
    float* d, const float4& a, const float2& b)
{
    asm volatile(
        "mma.sync.aligned.m16n8k8.row.col.f32.tf32.tf32.f32 "
        "{%0,%1,%2,%3}, {%4,%5,%6,%7}, {%8,%9}, {%0,%1,%2,%3};"
        : "+f"(d[0]), "+f"(d[1]), "+f"(d[2]), "+f"(d[3])
        : "r"(__float_as_uint(a.x)), "r"(__float_as_uint(a.y)),
          "r"(__float_as_uint(a.z)), "r"(__float_as_uint(a.w)),
          "r"(__float_as_uint(b.x)), "r"(__float_as_uint(b.y)));
}

// ===========================================================================
// Generic batched tf32 mma.sync GEMM.
//   TB=true : C = alpha * A @ B^T + bias   (B: [N,K] ldb)
//   TB=false: C = alpha * A @ B   + bias   (B: [K,N] ldb)
// BM=128, BK=32, 256 threads = 8 warps in WM x WN grid.
// SKIP_OUT: skip output tiles fully above diagonal.
// SKIP_K:   K loop limited to (mt+1)*BM (A rows zero beyond diagonal band).
// Smem tiles stored in mma fragment layout (scatter on store, vector LDS read):
//   A elem (mr, kc): lane=(mr&7)*4+(kc&3), r=(kc>>2)*2+(mr>>3)
//   B elem (kc, nr): lane=(nr&7)*4+(kc&3), r=kc>>2
// ===========================================================================
template<int BN, int WM, int WN, bool TB, bool SKIP_OUT, bool SKIP_K>
__global__ void __launch_bounds__(256)
gemm_mma_k(const float* __restrict__ A, const float* __restrict__ Bm,
           const float* __restrict__ bias, float* __restrict__ Cm,
           int K, int lda, int ldb, int ldc,
           long long sAb, long long sAh, long long sBb, long long sBh,
           long long sCb, long long sCh, int batchH, float alpha)
{
    constexpr int BM = 128, BK = 32;
    constexpr int MA = BM / WM / 16;
    constexpr int NA = BN / WN / 8;
    static_assert(WM * WN == 8, "8 warps");

    const int nt = blockIdx.x, mt = blockIdx.y;
    if (SKIP_OUT && nt > mt) return;
    const int z = blockIdx.z;
    const int b = z / batchH, h = z % batchH;
    const float* Az = A + b * sAb + h * sAh + (long long)mt * BM * lda;
    const float* Bz = Bm + b * sBb + h * sBh
                    + (TB ? (long long)nt * BN * ldb : (long long)nt * BN);
    float* Cz = Cm + b * sCb + h * sCh;

    __shared__ float sA[4][8][32][4];
    __shared__ float sB[4][BN / 8][32][2];

    const int tid = threadIdx.x, lane = tid & 31, w = tid >> 5;
    const int wm = w / WN, wn = w % WN;

    float acc[MA][NA][4];
#pragma unroll
    for (int i = 0; i < MA; i++)
#pragma unroll
        for (int j = 0; j < NA; j++)
#pragma unroll
            for (int r = 0; r < 4; r++) acc[i][j][r] = 0.f;

    const int kmax = SKIP_K ? (mt + 1) * BM : K;

    for (int k0 = 0; k0 < kmax; k0 += BK) {
        // ---- A tile: 128 rows x 32 k ----
#pragma unroll
        for (int i = 0; i < 4; i++) {
            int v = tid + i * 256;
            int row = v >> 3, c4 = v & 7;
            int ka = c4 >> 1;
            int r = (c4 & 1) * 2 + ((row >> 3) & 1);
            int ma = row >> 4, laneA = (row & 7) * 4;
            float4 t = *reinterpret_cast<const float4*>(
                &Az[(long long)row * lda + k0 + c4 * 4]);
            sA[ka][ma][laneA + 0][r] = f2tf32f(t.x);
            sA[ka][ma][laneA + 1][r] = f2tf32f(t.y);
            sA[ka][ma][laneA + 2][r] = f2tf32f(t.z);
            sA[ka][ma][laneA + 3][r] = f2tf32f(t.w);
        }
        // ---- B tile ----
        if constexpr (TB) {
#pragma unroll
            for (int i = 0; i < BN / 32; i++) {
                int v = tid + i * 256;
                int n = v >> 3, c4 = v & 7;
                int ka = c4 >> 1, r = c4 & 1;
                int na = n >> 3, laneB = (n & 7) * 4;
                float4 t = *reinterpret_cast<const float4*>(
                    &Bz[(long long)n * ldb + k0 + c4 * 4]);
                sB[ka][na][laneB + 0][r] = f2tf32f(t.x);
                sB[ka][na][laneB + 1][r] = f2tf32f(t.y);
                sB[ka][na][laneB + 2][r] = f2tf32f(t.z);
                sB[ka][na][laneB + 3][r] = f2tf32f(t.w);
            }
        } else {
#pragma unroll
            for (int i = 0; i < BN / 32; i++) {
                int v = tid + i * 256;
                int krow = v / (BN / 4);
                int nc = (v % (BN / 4)) * 4;
                int ka = krow >> 3, kc = krow & 7;
                int r = kc >> 2, lc = kc & 3;
                int na = nc >> 3, nb = nc & 7;
                float4 t = *reinterpret_cast<const float4*>(
                    &Bz[(long long)(k0 + krow) * ldb + nc]);
                sB[ka][na][(nb + 0) * 4 + lc][r] = f2tf32f(t.x);
                sB[ka][na][(nb + 1) * 4 + lc][r] = f2tf32f(t.y);
                sB[ka][na][(nb + 2) * 4 + lc][r] = f2tf32f(t.z);
                sB[ka][na][(nb + 3) * 4 + lc][r] = f2tf32f(t.w);
            }
        }
        __syncthreads();

#pragma unroll
        for (int ka = 0; ka < 4; ka++) {
            float4 aF[MA];
            float2 bF[NA];
#pragma unroll
            for (int i = 0; i < MA; i++)
                aF[i] = *reinterpret_cast<const float4*>(&sA[ka][wm * MA + i][lane][0]);
#pragma unroll
            for (int j = 0; j < NA; j++)
                bF[j] = *reinterpret_cast<const float2*>(&sB[ka][wn * NA + j][lane][0]);
#pragma unroll
            for (int i = 0; i < MA; i++)
#pragma unroll
                for (int j = 0; j < NA; j++)
                    mma_tf32_16x8x8(acc[i][j], aF[i], bF[j]);
        }
        __syncthreads();
    }

    // ---- epilogue ----
    const int m_base = mt * BM + wm * (MA * 16);
    const int n_base = nt * BN + wn * (NA * 8);
#pragma unroll
    for (int i = 0; i < MA; i++) {
        int row0 = m_base + i * 16 + (lane >> 2);
#pragma unroll
        for (int j = 0; j < NA; j++) {
            int col = n_base + j * 8 + (lane & 3) * 2;
            float b0 = bias ? bias[col] : 0.f;
            float b1 = bias ? bias[col + 1] : 0.f;
            float2 t0 = make_float2(acc[i][j][0] * alpha + b0,
                                    acc[i][j][1] * alpha + b1);
            float2 t1 = make_float2(acc[i][j][2] * alpha + b0,
                                    acc[i][j][3] * alpha + b1);
            *reinterpret_cast<float2*>(&Cz[(long long)row0 * ldc + col]) = t0;
            *reinterpret_cast<float2*>(&Cz[(long long)(row0 + 8) * ldc + col]) = t1;
        }
    }
}

// ===========================================================================
// Generic tiled FP32 GEMM (steps 1 & 2 — precision hedge)
// ===========================================================================
template<int BM, int BN, int BK, int TM, int TN, bool TB>
__global__ void __launch_bounds__((BM/TM)*(BN/TN))
gemm_k(const float* __restrict__ A, const float* __restrict__ Bm,
       const float* __restrict__ bias, float* __restrict__ Cm,
       int M, int N, int K, int lda, int ldb, int ldc, float alpha)
{
    constexpr int THREADS = (BM/TM)*(BN/TN);
    const int m0 = blockIdx.y * BM;
    const int n0 = blockIdx.x * BN;

    __shared__ float As[BK][BM];
    __shared__ float Bs[BK][BN];

    const int tid = threadIdx.x;
    float acc[TM][TN];
#pragma unroll
    for (int i = 0; i < TM; i++)
#pragma unroll
        for (int j = 0; j < TN; j++) acc[i][j] = 0.f;

    constexpr int A_PER = BM * BK / 4 / THREADS;
    constexpr int B_PER = BN * BK / 4 / THREADS;

    const int tr = (tid / (BN/TN)) * TM;
    const int tc = (tid % (BN/TN)) * TN;

    for (int k0 = 0; k0 < K; k0 += BK) {
#pragma unroll
        for (int i = 0; i < A_PER; i++) {
            int v   = tid + i * THREADS;
            int row = v / (BK/4);
            int kc  = (v % (BK/4)) * 4;
            float4 t = *reinterpret_cast<const float4*>(
                &A[(long long)(m0 + row) * lda + k0 + kc]);
            As[kc+0][row] = t.x; As[kc+1][row] = t.y;
            As[kc+2][row] = t.z; As[kc+3][row] = t.w;
        }
        if constexpr (TB) {
#pragma unroll
            for (int i = 0; i < B_PER; i++) {
                int v   = tid + i * THREADS;
                int row = v / (BK/4);
                int kc  = (v % (BK/4)) * 4;
                float4 t = *reinterpret_cast<const float4*>(
                    &Bm[(long long)(n0 + row) * ldb + k0 + kc]);
                Bs[kc+0][row] = t.x; Bs[kc+1][row] = t.y;
                Bs[kc+2][row] = t.z; Bs[kc+3][row] = t.w;
            }
        } else {
#pragma unroll
            for (int i = 0; i < B_PER; i++) {
                int v    = tid + i * THREADS;
                int krow = v / (BN/4);
                int nc   = (v % (BN/4)) * 4;
                float4 t = *reinterpret_cast<const float4*>(
                    &Bm[(long long)(k0 + krow) * ldb + n0 + nc]);
                *reinterpret_cast<float4*>(&Bs[krow][nc]) = t;
            }
        }
        __syncthreads();

#pragma unroll
        for (int kk = 0; kk < BK; kk++) {
            float ar[TM], br[TN];
#pragma unroll
            for (int i = 0; i < TM; i++) ar[i] = As[kk][tr + i];
#pragma unroll
            for (int j = 0; j < TN; j++) br[j] = Bs[kk][tc + j];
#pragma unroll
            for (int i = 0; i < TM; i++)
#pragma unroll
                for (int j = 0; j < TN; j++)
                    acc[i][j] += ar[i] * br[j];
        }
        __syncthreads();
    }

#pragma unroll
    for (int i = 0; i < TM; i++) {
        long long crow = (long long)(m0 + tr + i) * ldc + n0 + tc;
#pragma unroll
        for (int j = 0; j < TN; j += 4) {
            float4 t;
            t.x = acc[i][j+0] * alpha + (bias ? bias[n0 + tc + j + 0] : 0.f);
            t.y = acc[i][j+1] * alpha + (bias ? bias[n0 + tc + j + 1] : 0.f);
            t.z = acc[i][j+2] * alpha + (bias ? bias[n0 + tc + j + 2] : 0.f);
            t.w = acc[i][j+3] * alpha + (bias ? bias[n0 + tc + j + 3] : 0.f);
            *reinterpret_cast<float4*>(&Cm[crow + j]) = t;
        }
    }
}

// ---------------------------------------------------------------------------
// Causal softmax with smem row cache; writes only the diagonal 128-band
// (step 6's K-skip never reads beyond it).
// ---------------------------------------------------------------------------
__device__ __forceinline__ float warp_max(float v) {
#pragma unroll
    for (int o = 16; o; o >>= 1) v = fmaxf(v, __shfl_xor_sync(0xffffffffu, v, o));
    return v;
}
__device__ __forceinline__ float warp_sum(float v) {
#pragma unroll
    for (int o = 16; o; o >>= 1) v += __shfl_xor_sync(0xffffffffu, v, o);
    return v;
}

__global__ void __launch_bounds__(256)
softmax_causal_k(float* __restrict__ att)
{
    const long long z = blockIdx.y;
    const int q = blockIdx.x;
    float* row = att + (z * TT + q) * (long long)TT;
    const int L = q + 1;
    const int tid = threadIdx.x;
    __shared__ float srow[TT];
    __shared__ float red[8];

    float m = -INFINITY;
    for (int j = tid; j < L; j += 256) {
        float v = row[j];
        srow[j] = v;
        m = fmaxf(m, v);
    }
    m = warp_max(m);
    if ((tid & 31) == 0) red[tid >> 5] = m;
    __syncthreads();
    if (tid < 32) {
        float v = (tid < 8) ? red[tid] : -INFINITY;
        v = warp_max(v);
        if (tid == 0) red[0] = v;
    }
    __syncthreads();
    const float mg = red[0];
    __syncthreads();

    float s = 0.f;
    for (int j = tid; j < L; j += 256) {
        float e = __expf(srow[j] - mg);
        srow[j] = e;
        s += e;
    }
    s = warp_sum(s);
    if ((tid & 31) == 0) red[tid >> 5] = s;
    __syncthreads();
    if (tid < 32) {
        float v = (tid < 8) ? red[tid] : 0.f;
        v = warp_sum(v);
        if (tid == 0) red[0] = v;
    }
    __syncthreads();
    const float inv = 1.f / red[0];

    const int wlimit = ((q >> 7) + 1) << 7;
    for (int j = tid; j < wlimit; j += 256)
        row[j] = (j < L) ? srow[j] * inv : 0.f;
}

// ---------------------------------------------------------------------------
extern "C" void kernel_launch(void* const* d_in, const int* in_sizes, int n_in,
                              void* d_out, int out_size)
{
    const float* x  = (const float*)d_in[0];
    const float* Wv = (const float*)d_in[1];
    const float* bv = (const float*)d_in[2];
    const float* Wl = (const float*)d_in[3];
    const float* Wc = (const float*)d_in[4];
    const float* bc = (const float*)d_in[5];
    const float* Wp = (const float*)d_in[6];
    const float* bp = (const float*)d_in[7];
    float* out = (float*)d_out;

    float *v_p, *u_p, *att2_p, *wcl_p, *y_p;
    cudaGetSymbolAddress((void**)&v_p,    g_v);
    cudaGetSymbolAddress((void**)&u_p,    g_u);
    cudaGetSymbolAddress((void**)&att2_p, g_att2);
    cudaGetSymbolAddress((void**)&wcl_p,  g_wcl);
    cudaGetSymbolAddress((void**)&y_p,    g_y);

    const long long sTT  = (long long)TT * TT;       // att2 head stride
    const long long sBTC = (long long)TT * CC;       // v/y batch stride
    const long long sUh  = (long long)TT * HDD;      // u head stride
    const long long sUb  = (long long)NHH * sUh;     // u batch stride

    // 1) Wcl = Wc @ Wl   (fp32, 2.1 GF)
    gemm_k<128,128,16,8,8,false><<<dim3(8,8,1),256>>>(
        Wc, Wl, nullptr, wcl_p, TT, TT, TT, TT, TT, TT, 1.0f);

    // 2) v = x @ Wv^T + bv   (fp32 — v feeds q, k, v; keep exact)
    gemm_k<128,128,16,8,8,true><<<dim3(CC/128, (BB*TT)/128, 1),256>>>(
        x, Wv, bv, v_p, BB*TT, CC, CC, CC, CC, CC, 1.0f);

    // 3) u = Wcl @ vh   per (b,h)  (tf32 NN, K=1024, N=64)
    //    Identity: att2 = (vh vh^T/8) Wcl^T + bc = vh (Wcl vh)^T /8 + bc.
    //    Kills the O(T^3) mixing GEMM: 103 GF -> 20 GF across steps 3+4.
    gemm_mma_k<64,4,2,false,false,false><<<dim3(1,8,BB*NHH),256>>>(
        wcl_p, v_p, nullptr, u_p,
        TT, TT, CC, HDD,
        0,0, sBTC, HDD, sUb, sUh,
        NHH, 1.0f);

    // 4) att2 = vh @ u^T / 8 + bc   (tf32 NT, K=64, causal tile skip)
    gemm_mma_k<128,2,4,true,true,false><<<dim3(8,8,BB*NHH),256>>>(
        v_p, u_p, bc, att2_p,
        HDD, CC, HDD, TT,
        sBTC, HDD, sUb, sUh, (long long)NHH*sTT, sTT,
        NHH, 0.125f);

    // 5) causal softmax in-place on att2
    softmax_causal_k<<<dim3(TT, BB*NHH), 256>>>(att2_p);

    // 6) y = att2 @ vh   (tf32 NN, N=64, causal K-skip)
    gemm_mma_k<64,4,2,false,false,true><<<dim3(1,8,BB*NHH),256>>>(
        att2_p, v_p, nullptr, y_p,
        TT, TT, CC, CC,
        (long long)NHH*sTT, sTT, sBTC, HDD, sBTC, HDD,
        NHH, 1.0f);

    // 7) out = y @ Wp^T + bp   (tf32 NT)
    gemm_mma_k<128,2,4,true,false,false><<<dim3(CC/128, (BB*TT)/128, 1),256>>>(
        y_p, Wp, bp, out,
        CC, CC, CC, CC,
        0,0, 0,0, 0,0, 1, 1.0f);
}

// round 8
// speedup vs baseline: 3.7684x; 1.2039x over previous
#include <cuda_runtime.h>
#include <math.h>
#include <stdint.h>

// Problem constants
#define BB 8
#define TT 1024
#define CC 768
#define NHH 12
#define HDD 64

// Scratch (static __device__ arrays: no allocation allowed)
__device__ float g_v  [BB * TT * CC];                   // value projection [B,T,C]
__device__ float g_u  [BB * TT * CC];                   // u = Wcl @ v  [B,T,C] (head-merged)
__device__ float g_att2[(long long)BB * NHH * TT * TT]; // logits / probs
__device__ float g_wcl[TT * TT];                        // Wc @ Wl
__device__ float g_y  [BB * TT * CC];                   // attention output [B,T,C]

// ===========================================================================
// tf32 helpers (base sm_80+ ISA — harness compiles compute_103, no tcgen05)
// ===========================================================================
__device__ __forceinline__ float f2tf32f(float x) {
    uint32_t u;
    asm("cvt.rna.tf32.f32 %0, %1;" : "=r"(u) : "f"(x));
    return __uint_as_float(u);
}

__device__ __forceinline__ void mma_tf32_16x8x8(
    float* d, const float4& a, const float2& b)
{
    asm volatile(
        "mma.sync.aligned.m16n8k8.row.col.f32.tf32.tf32.f32 "
        "{%0,%1,%2,%3}, {%4,%5,%6,%7}, {%8,%9}, {%0,%1,%2,%3};"
        : "+f"(d[0]), "+f"(d[1]), "+f"(d[2]), "+f"(d[3])
        : "r"(__float_as_uint(a.x)), "r"(__float_as_uint(a.y)),
          "r"(__float_as_uint(a.z)), "r"(__float_as_uint(a.w)),
          "r"(__float_as_uint(b.x)), "r"(__float_as_uint(b.y)));
}

// ===========================================================================
// Generic batched tf32 mma.sync GEMM (engine unchanged from R7).
//   TB=true : C = alpha * A @ B^T + bias   (B: [N,K] ldb)
//   TB=false: C = alpha * A @ B   + bias   (B: [K,N] ldb)
// BM=128, BK=32, 256 threads = 8 warps in WM x WN grid.
// SKIP_OUT: skip output tiles fully above diagonal.
// SKIP_K:   K loop limited to (mt+1)*BM (A rows zero beyond diagonal band).
// ===========================================================================
template<int BN, int WM, int WN, bool TB, bool SKIP_OUT, bool SKIP_K>
__global__ void __launch_bounds__(256)
gemm_mma_k(const float* __restrict__ A, const float* __restrict__ Bm,
           const float* __restrict__ bias, float* __restrict__ Cm,
           int K, int lda, int ldb, int ldc,
           long long sAb, long long sAh, long long sBb, long long sBh,
           long long sCb, long long sCh, int batchH, float alpha)
{
    constexpr int BM = 128, BK = 32;
    constexpr int MA = BM / WM / 16;
    constexpr int NA = BN / WN / 8;
    static_assert(WM * WN == 8, "8 warps");

    const int nt = blockIdx.x, mt = blockIdx.y;
    if (SKIP_OUT && nt > mt) return;
    const int z = blockIdx.z;
    const int b = z / batchH, h = z % batchH;
    const float* Az = A + b * sAb + h * sAh + (long long)mt * BM * lda;
    const float* Bz = Bm + b * sBb + h * sBh
                    + (TB ? (long long)nt * BN * ldb : (long long)nt * BN);
    float* Cz = Cm + b * sCb + h * sCh;

    __shared__ float sA[4][8][32][4];
    __shared__ float sB[4][BN / 8][32][2];

    const int tid = threadIdx.x, lane = tid & 31, w = tid >> 5;
    const int wm = w / WN, wn = w % WN;

    float acc[MA][NA][4];
#pragma unroll
    for (int i = 0; i < MA; i++)
#pragma unroll
        for (int j = 0; j < NA; j++)
#pragma unroll
            for (int r = 0; r < 4; r++) acc[i][j][r] = 0.f;

    const int kmax = SKIP_K ? (mt + 1) * BM : K;

    for (int k0 = 0; k0 < kmax; k0 += BK) {
        // ---- A tile: 128 rows x 32 k ----
#pragma unroll
        for (int i = 0; i < 4; i++) {
            int v = tid + i * 256;
            int row = v >> 3, c4 = v & 7;
            int ka = c4 >> 1;
            int r = (c4 & 1) * 2 + ((row >> 3) & 1);
            int ma = row >> 4, laneA = (row & 7) * 4;
            float4 t = *reinterpret_cast<const float4*>(
                &Az[(long long)row * lda + k0 + c4 * 4]);
            sA[ka][ma][laneA + 0][r] = f2tf32f(t.x);
            sA[ka][ma][laneA + 1][r] = f2tf32f(t.y);
            sA[ka][ma][laneA + 2][r] = f2tf32f(t.z);
            sA[ka][ma][laneA + 3][r] = f2tf32f(t.w);
        }
        // ---- B tile ----
        if constexpr (TB) {
#pragma unroll
            for (int i = 0; i < BN / 32; i++) {
                int v = tid + i * 256;
                int n = v >> 3, c4 = v & 7;
                int ka = c4 >> 1, r = c4 & 1;
                int na = n >> 3, laneB = (n & 7) * 4;
                float4 t = *reinterpret_cast<const float4*>(
                    &Bz[(long long)n * ldb + k0 + c4 * 4]);
                sB[ka][na][laneB + 0][r] = f2tf32f(t.x);
                sB[ka][na][laneB + 1][r] = f2tf32f(t.y);
                sB[ka][na][laneB + 2][r] = f2tf32f(t.z);
                sB[ka][na][laneB + 3][r] = f2tf32f(t.w);
            }
        } else {
#pragma unroll
            for (int i = 0; i < BN / 32; i++) {
                int v = tid + i * 256;
                int krow = v / (BN / 4);
                int nc = (v % (BN / 4)) * 4;
                int ka = krow >> 3, kc = krow & 7;
                int r = kc >> 2, lc = kc & 3;
                int na = nc >> 3, nb = nc & 7;
                float4 t = *reinterpret_cast<const float4*>(
                    &Bz[(long long)(k0 + krow) * ldb + nc]);
                sB[ka][na][(nb + 0) * 4 + lc][r] = f2tf32f(t.x);
                sB[ka][na][(nb + 1) * 4 + lc][r] = f2tf32f(t.y);
                sB[ka][na][(nb + 2) * 4 + lc][r] = f2tf32f(t.z);
                sB[ka][na][(nb + 3) * 4 + lc][r] = f2tf32f(t.w);
            }
        }
        __syncthreads();

#pragma unroll
        for (int ka = 0; ka < 4; ka++) {
            float4 aF[MA];
            float2 bF[NA];
#pragma unroll
            for (int i = 0; i < MA; i++)
                aF[i] = *reinterpret_cast<const float4*>(&sA[ka][wm * MA + i][lane][0]);
#pragma unroll
            for (int j = 0; j < NA; j++)
                bF[j] = *reinterpret_cast<const float2*>(&sB[ka][wn * NA + j][lane][0]);
#pragma unroll
            for (int i = 0; i < MA; i++)
#pragma unroll
                for (int j = 0; j < NA; j++)
                    mma_tf32_16x8x8(acc[i][j], aF[i], bF[j]);
        }
        __syncthreads();
    }

    // ---- epilogue ----
    const int m_base = mt * BM + wm * (MA * 16);
    const int n_base = nt * BN + wn * (NA * 8);
#pragma unroll
    for (int i = 0; i < MA; i++) {
        int row0 = m_base + i * 16 + (lane >> 2);
#pragma unroll
        for (int j = 0; j < NA; j++) {
            int col = n_base + j * 8 + (lane & 3) * 2;
            float b0 = bias ? bias[col] : 0.f;
            float b1 = bias ? bias[col + 1] : 0.f;
            float2 t0 = make_float2(acc[i][j][0] * alpha + b0,
                                    acc[i][j][1] * alpha + b1);
            float2 t1 = make_float2(acc[i][j][2] * alpha + b0,
                                    acc[i][j][3] * alpha + b1);
            *reinterpret_cast<float2*>(&Cz[(long long)row0 * ldc + col]) = t0;
            *reinterpret_cast<float2*>(&Cz[(long long)(row0 + 8) * ldc + col]) = t1;
        }
    }
}

// ---------------------------------------------------------------------------
// Causal softmax: one warp per row, row cached in 32 registers.
// Writes only the diagonal 128-band (step 6's K-skip never reads beyond it).
// Block = 8 warps = 8 consecutive rows of one z.
// ---------------------------------------------------------------------------
__global__ void __launch_bounds__(256)
softmax_causal_warp_k(float* __restrict__ att)
{
    const long long z = blockIdx.y;
    const int q = blockIdx.x * 8 + (threadIdx.x >> 5);
    const int lane = threadIdx.x & 31;
    float* row = att + (z * TT + q) * (long long)TT;
    const int L = q + 1;
    const int wlimit = ((q >> 7) + 1) << 7;

    float r[32];
    float m = -INFINITY;
#pragma unroll
    for (int jj = 0; jj < 32; jj++) {
        int j = lane + jj * 32;
        float v = (j < L) ? row[j] : -INFINITY;
        r[jj] = v;
        m = fmaxf(m, v);
    }
#pragma unroll
    for (int o = 16; o; o >>= 1) m = fmaxf(m, __shfl_xor_sync(0xffffffffu, m, o));

    float s = 0.f;
#pragma unroll
    for (int jj = 0; jj < 32; jj++) {
        int j = lane + jj * 32;
        float e = (j < L) ? __expf(r[jj] - m) : 0.f;
        r[jj] = e;
        s += e;
    }
#pragma unroll
    for (int o = 16; o; o >>= 1) s += __shfl_xor_sync(0xffffffffu, s, o);
    const float inv = 1.f / s;

#pragma unroll
    for (int jj = 0; jj < 32; jj++) {
        int j = lane + jj * 32;
        if (j < wlimit) row[j] = r[jj] * inv;   // r[jj]=0 for j>=L (mask zeros)
    }
}

// ---------------------------------------------------------------------------
extern "C" void kernel_launch(void* const* d_in, const int* in_sizes, int n_in,
                              void* d_out, int out_size)
{
    const float* x  = (const float*)d_in[0];
    const float* Wv = (const float*)d_in[1];
    const float* bv = (const float*)d_in[2];
    const float* Wl = (const float*)d_in[3];
    const float* Wc = (const float*)d_in[4];
    const float* bc = (const float*)d_in[5];
    const float* Wp = (const float*)d_in[6];
    const float* bp = (const float*)d_in[7];
    float* out = (float*)d_out;

    float *v_p, *u_p, *att2_p, *wcl_p, *y_p;
    cudaGetSymbolAddress((void**)&v_p,    g_v);
    cudaGetSymbolAddress((void**)&u_p,    g_u);
    cudaGetSymbolAddress((void**)&att2_p, g_att2);
    cudaGetSymbolAddress((void**)&wcl_p,  g_wcl);
    cudaGetSymbolAddress((void**)&y_p,    g_y);

    const long long sTT  = (long long)TT * TT;       // att2 head stride
    const long long sBTC = (long long)TT * CC;       // v/u/y batch stride

    // 1) Wcl = Wc @ Wl   (tf32 NN, 2.1 GF — consumers already round to tf32)
    gemm_mma_k<128,2,4,false,false,false><<<dim3(8,8,1),256>>>(
        Wc, Wl, nullptr, wcl_p,
        TT, TT, TT, TT,
        0,0, 0,0, 0,0, 1, 1.0f);

    // 2) v = x @ Wv^T + bv   (tf32 NT — v is tf32-rounded at every consumer
    //    anyway; only the projection accumulation error is new)
    gemm_mma_k<128,2,4,true,false,false><<<dim3(CC/128, (BB*TT)/128, 1),256>>>(
        x, Wv, bv, v_p,
        CC, CC, CC, CC,
        0,0, 0,0, 0,0, 1, 1.0f);

    // 3) u[b] = Wcl @ v[b]   (tf32 NN, head-merged: N=768 wide, [B,T,C] layout)
    //    Identity: att2 = (vh vh^T/8) Wcl^T + bc = vh (Wcl vh)^T /8 + bc,
    //    and Wcl @ vh for all heads at once = Wcl @ v[b].
    gemm_mma_k<128,2,4,false,false,false><<<dim3(CC/128, 8, BB),256>>>(
        wcl_p, v_p, nullptr, u_p,
        TT, TT, CC, CC,
        0,0, sBTC,0, sBTC,0, 1, 1.0f);

    // 4) att2 = vh @ uh^T / 8 + bc   (tf32 NT, K=64, causal tile skip)
    gemm_mma_k<128,2,4,true,true,false><<<dim3(8,8,BB*NHH),256>>>(
        v_p, u_p, bc, att2_p,
        HDD, CC, CC, TT,
        sBTC, HDD, sBTC, HDD, (long long)NHH*sTT, sTT,
        NHH, 0.125f);

    // 5) causal softmax in-place on att2 (warp-per-row, band-limited writes)
    softmax_causal_warp_k<<<dim3(TT/8, BB*NHH), 256>>>(att2_p);

    // 6) y = att2 @ vh   (tf32 NN, N=64, causal K-skip)
    gemm_mma_k<64,4,2,false,false,true><<<dim3(1,8,BB*NHH),256>>>(
        att2_p, v_p, nullptr, y_p,
        TT, TT, CC, CC,
        (long long)NHH*sTT, sTT, sBTC, HDD, sBTC, HDD,
        NHH, 1.0f);

    // 7) out = y @ Wp^T + bp   (tf32 NT)
    gemm_mma_k<128,2,4,true,false,false><<<dim3(CC/128, (BB*TT)/128, 1),256>>>(
        y_p, Wp, bp, out,
        CC, CC, CC, CC,
        0,0, 0,0, 0,0, 1, 1.0f);
}

// round 9
// speedup vs baseline: 3.9075x; 1.0369x over previous
#include <cuda_runtime.h>
#include <math.h>
#include <stdint.h>

// Problem constants
#define BB 8
#define TT 1024
#define CC 768
#define NHH 12
#define HDD 64

// Scratch (static __device__ arrays: no allocation allowed)
__device__ float g_v  [BB * TT * CC];                   // value projection [B,T,C]
__device__ float g_u  [BB * TT * CC];                   // u = Wcl @ v  [B,T,C]
__device__ float g_att2[(long long)BB * NHH * TT * TT]; // raw logits (never softmaxed in place)
__device__ float g_wcl[TT * TT];                        // Wc @ Wl
__device__ float g_y  [BB * TT * CC];                   // attention output [B,T,C]

// ===========================================================================
// tf32 helpers (base sm_80+ ISA — harness compiles compute_103, no tcgen05)
// ===========================================================================
__device__ __forceinline__ float f2tf32f(float x) {
    uint32_t u;
    asm("cvt.rna.tf32.f32 %0, %1;" : "=r"(u) : "f"(x));
    return __uint_as_float(u);
}

__device__ __forceinline__ void mma_tf32_16x8x8(
    float* d, const float4& a, const float2& b)
{
    asm volatile(
        "mma.sync.aligned.m16n8k8.row.col.f32.tf32.tf32.f32 "
        "{%0,%1,%2,%3}, {%4,%5,%6,%7}, {%8,%9}, {%0,%1,%2,%3};"
        : "+f"(d[0]), "+f"(d[1]), "+f"(d[2]), "+f"(d[3])
        : "r"(__float_as_uint(a.x)), "r"(__float_as_uint(a.y)),
          "r"(__float_as_uint(a.z)), "r"(__float_as_uint(a.w)),
          "r"(__float_as_uint(b.x)), "r"(__float_as_uint(b.y)));
}

// ===========================================================================
// Generic batched tf32 mma.sync GEMM (engine unchanged from R8).
// ===========================================================================
template<int BN, int WM, int WN, bool TB, bool SKIP_OUT, bool SKIP_K>
__global__ void __launch_bounds__(256)
gemm_mma_k(const float* __restrict__ A, const float* __restrict__ Bm,
           const float* __restrict__ bias, float* __restrict__ Cm,
           int K, int lda, int ldb, int ldc,
           long long sAb, long long sAh, long long sBb, long long sBh,
           long long sCb, long long sCh, int batchH, float alpha)
{
    constexpr int BM = 128, BK = 32;
    constexpr int MA = BM / WM / 16;
    constexpr int NA = BN / WN / 8;
    static_assert(WM * WN == 8, "8 warps");

    const int nt = blockIdx.x, mt = blockIdx.y;
    if (SKIP_OUT && nt > mt) return;
    const int z = blockIdx.z;
    const int b = z / batchH, h = z % batchH;
    const float* Az = A + b * sAb + h * sAh + (long long)mt * BM * lda;
    const float* Bz = Bm + b * sBb + h * sBh
                    + (TB ? (long long)nt * BN * ldb : (long long)nt * BN);
    float* Cz = Cm + b * sCb + h * sCh;

    __shared__ float sA[4][8][32][4];
    __shared__ float sB[4][BN / 8][32][2];

    const int tid = threadIdx.x, lane = tid & 31, w = tid >> 5;
    const int wm = w / WN, wn = w % WN;

    float acc[MA][NA][4];
#pragma unroll
    for (int i = 0; i < MA; i++)
#pragma unroll
        for (int j = 0; j < NA; j++)
#pragma unroll
            for (int r = 0; r < 4; r++) acc[i][j][r] = 0.f;

    const int kmax = SKIP_K ? (mt + 1) * BM : K;

    for (int k0 = 0; k0 < kmax; k0 += BK) {
#pragma unroll
        for (int i = 0; i < 4; i++) {
            int v = tid + i * 256;
            int row = v >> 3, c4 = v & 7;
            int ka = c4 >> 1;
            int r = (c4 & 1) * 2 + ((row >> 3) & 1);
            int ma = row >> 4, laneA = (row & 7) * 4;
            float4 t = *reinterpret_cast<const float4*>(
                &Az[(long long)row * lda + k0 + c4 * 4]);
            sA[ka][ma][laneA + 0][r] = f2tf32f(t.x);
            sA[ka][ma][laneA + 1][r] = f2tf32f(t.y);
            sA[ka][ma][laneA + 2][r] = f2tf32f(t.z);
            sA[ka][ma][laneA + 3][r] = f2tf32f(t.w);
        }
        if constexpr (TB) {
#pragma unroll
            for (int i = 0; i < BN / 32; i++) {
                int v = tid + i * 256;
                int n = v >> 3, c4 = v & 7;
                int ka = c4 >> 1, r = c4 & 1;
                int na = n >> 3, laneB = (n & 7) * 4;
                float4 t = *reinterpret_cast<const float4*>(
                    &Bz[(long long)n * ldb + k0 + c4 * 4]);
                sB[ka][na][laneB + 0][r] = f2tf32f(t.x);
                sB[ka][na][laneB + 1][r] = f2tf32f(t.y);
                sB[ka][na][laneB + 2][r] = f2tf32f(t.z);
                sB[ka][na][laneB + 3][r] = f2tf32f(t.w);
            }
        } else {
#pragma unroll
            for (int i = 0; i < BN / 32; i++) {
                int v = tid + i * 256;
                int krow = v / (BN / 4);
                int nc = (v % (BN / 4)) * 4;
                int ka = krow >> 3, kc = krow & 7;
                int r = kc >> 2, lc = kc & 3;
                int na = nc >> 3, nb = nc & 7;
                float4 t = *reinterpret_cast<const float4*>(
                    &Bz[(long long)(k0 + krow) * ldb + nc]);
                sB[ka][na][(nb + 0) * 4 + lc][r] = f2tf32f(t.x);
                sB[ka][na][(nb + 1) * 4 + lc][r] = f2tf32f(t.y);
                sB[ka][na][(nb + 2) * 4 + lc][r] = f2tf32f(t.z);
                sB[ka][na][(nb + 3) * 4 + lc][r] = f2tf32f(t.w);
            }
        }
        __syncthreads();

#pragma unroll
        for (int ka = 0; ka < 4; ka++) {
            float4 aF[MA];
            float2 bF[NA];
#pragma unroll
            for (int i = 0; i < MA; i++)
                aF[i] = *reinterpret_cast<const float4*>(&sA[ka][wm * MA + i][lane][0]);
#pragma unroll
            for (int j = 0; j < NA; j++)
                bF[j] = *reinterpret_cast<const float2*>(&sB[ka][wn * NA + j][lane][0]);
#pragma unroll
            for (int i = 0; i < MA; i++)
#pragma unroll
                for (int j = 0; j < NA; j++)
                    mma_tf32_16x8x8(acc[i][j], aF[i], bF[j]);
        }
        __syncthreads();
    }

    const int m_base = mt * BM + wm * (MA * 16);
    const int n_base = nt * BN + wn * (NA * 8);
#pragma unroll
    for (int i = 0; i < MA; i++) {
        int row0 = m_base + i * 16 + (lane >> 2);
#pragma unroll
        for (int j = 0; j < NA; j++) {
            int col = n_base + j * 8 + (lane & 3) * 2;
            float b0 = bias ? bias[col] : 0.f;
            float b1 = bias ? bias[col + 1] : 0.f;
            float2 t0 = make_float2(acc[i][j][0] * alpha + b0,
                                    acc[i][j][1] * alpha + b1);
            float2 t1 = make_float2(acc[i][j][2] * alpha + b0,
                                    acc[i][j][3] * alpha + b1);
            *reinterpret_cast<float2*>(&Cz[(long long)row0 * ldc + col]) = t0;
            *reinterpret_cast<float2*>(&Cz[(long long)(row0 + 8) * ldc + col]) = t1;
        }
    }
}

// ===========================================================================
// Fused step 5+6: y[z] = softmax_causal(att2_logits[z]) @ vh[z]
// Online (flash-style) softmax inside the K loop over key tiles.
// BM=128 q rows, BN=64 (HD), BK=32, 8 warps: WM=4 x WN=2 -> MA=2, NA=4.
// Row stats (max, sum) are intra-warp: reduce within thread + 2 quad shuffles.
// Diagonal k-tiles masked per fragment element (col > row -> -1e30).
// ===========================================================================
__global__ void __launch_bounds__(256)
attnv_fused_k(const float* __restrict__ att2, const float* __restrict__ vv,
              float* __restrict__ yy)
{
    constexpr int MA = 2, NA = 4;
    const int mt = blockIdx.y;
    const int z = blockIdx.z;
    const int b = z / NHH, h = z % NHH;

    const float* Az = att2 + (long long)z * TT * TT + (long long)mt * 128 * TT;
    const float* Bz = vv + (long long)b * TT * CC + h * HDD;
    float* Cz = yy + (long long)b * TT * CC + h * HDD;

    __shared__ float sA[4][8][32][4];   // raw fp32 logits in A-frag layout
    __shared__ float sB[4][8][32][2];   // v tile (tf32) in B-frag layout

    const int tid = threadIdx.x, lane = tid & 31, w = tid >> 5;
    const int wm = w >> 1, wn = w & 1;
    const int g = lane >> 2, lq = lane & 3;

    float acc[MA][NA][4];
    float mrun[MA][2], lrun[MA][2];
#pragma unroll
    for (int i = 0; i < MA; i++) {
        mrun[i][0] = mrun[i][1] = -INFINITY;
        lrun[i][0] = lrun[i][1] = 0.f;
#pragma unroll
        for (int j = 0; j < NA; j++)
#pragma unroll
            for (int r = 0; r < 4; r++) acc[i][j][r] = 0.f;
    }

    const int kmax = (mt + 1) * 128;

    for (int k0 = 0; k0 < kmax; k0 += 32) {
        // ---- load logits tile (raw fp32, A-frag scatter) ----
#pragma unroll
        for (int i = 0; i < 4; i++) {
            int v = tid + i * 256;
            int row = v >> 3, c4 = v & 7;
            int ka = c4 >> 1;
            int r = (c4 & 1) * 2 + ((row >> 3) & 1);
            int ma = row >> 4, laneA = (row & 7) * 4;
            float4 t = *reinterpret_cast<const float4*>(
                &Az[(long long)row * TT + k0 + c4 * 4]);
            sA[ka][ma][laneA + 0][r] = t.x;
            sA[ka][ma][laneA + 1][r] = t.y;
            sA[ka][ma][laneA + 2][r] = t.z;
            sA[ka][ma][laneA + 3][r] = t.w;
        }
        // ---- load v tile (B-frag NN scatter, tf32) ----
#pragma unroll
        for (int i = 0; i < 2; i++) {
            int v = tid + i * 256;
            int krow = v >> 4;            // / (BN/4 = 16)
            int nc = (v & 15) * 4;
            int ka = krow >> 3, kc = krow & 7;
            int r = kc >> 2, lc = kc & 3;
            int na = nc >> 3, nb = nc & 7;
            float4 t = *reinterpret_cast<const float4*>(
                &Bz[(long long)(k0 + krow) * CC + nc]);
            sB[ka][na][(nb + 0) * 4 + lc][r] = f2tf32f(t.x);
            sB[ka][na][(nb + 1) * 4 + lc][r] = f2tf32f(t.y);
            sB[ka][na][(nb + 2) * 4 + lc][r] = f2tf32f(t.z);
            sB[ka][na][(nb + 3) * 4 + lc][r] = f2tf32f(t.w);
        }
        __syncthreads();

        // preload B frags (reused for both m-atoms)
        float2 bF[4][NA];
#pragma unroll
        for (int ka = 0; ka < 4; ka++)
#pragma unroll
            for (int j = 0; j < NA; j++)
                bF[ka][j] = *reinterpret_cast<const float2*>(&sB[ka][wn * NA + j][lane][0]);

        const bool diag = (k0 >= mt * 128);

#pragma unroll
        for (int i = 0; i < MA; i++) {
            const int r0 = mt * 128 + (wm * MA + i) * 16 + g;  // row of a0/a2
            // ---- pass 1: tile row max ----
            float tm0 = -INFINITY, tm1 = -INFINITY;
#pragma unroll
            for (int ka = 0; ka < 4; ka++) {
                float4 a = *reinterpret_cast<const float4*>(&sA[ka][wm * MA + i][lane][0]);
                if (diag) {
                    int cb = k0 + ka * 8 + lq;
                    if (cb > r0)         a.x = -1e30f;
                    if (cb + 4 > r0)     a.z = -1e30f;
                    if (cb > r0 + 8)     a.y = -1e30f;
                    if (cb + 4 > r0 + 8) a.w = -1e30f;
                }
                tm0 = fmaxf(tm0, fmaxf(a.x, a.z));
                tm1 = fmaxf(tm1, fmaxf(a.y, a.w));
            }
            tm0 = fmaxf(tm0, __shfl_xor_sync(0xffffffffu, tm0, 1));
            tm0 = fmaxf(tm0, __shfl_xor_sync(0xffffffffu, tm0, 2));
            tm1 = fmaxf(tm1, __shfl_xor_sync(0xffffffffu, tm1, 1));
            tm1 = fmaxf(tm1, __shfl_xor_sync(0xffffffffu, tm1, 2));

            const float nm0 = fmaxf(mrun[i][0], tm0);
            const float nm1 = fmaxf(mrun[i][1], tm1);
            const float sc0 = __expf(mrun[i][0] - nm0);
            const float sc1 = __expf(mrun[i][1] - nm1);
            mrun[i][0] = nm0; mrun[i][1] = nm1;
            lrun[i][0] *= sc0; lrun[i][1] *= sc1;
#pragma unroll
            for (int j = 0; j < NA; j++) {
                acc[i][j][0] *= sc0; acc[i][j][1] *= sc0;
                acc[i][j][2] *= sc1; acc[i][j][3] *= sc1;
            }

            // ---- pass 2: exp, row sum, MMA ----
            float ts0 = 0.f, ts1 = 0.f;
#pragma unroll
            for (int ka = 0; ka < 4; ka++) {
                float4 a = *reinterpret_cast<const float4*>(&sA[ka][wm * MA + i][lane][0]);
                if (diag) {
                    int cb = k0 + ka * 8 + lq;
                    if (cb > r0)         a.x = -1e30f;
                    if (cb + 4 > r0)     a.z = -1e30f;
                    if (cb > r0 + 8)     a.y = -1e30f;
                    if (cb + 4 > r0 + 8) a.w = -1e30f;
                }
                float4 p;
                p.x = __expf(a.x - nm0); p.z = __expf(a.z - nm0);
                p.y = __expf(a.y - nm1); p.w = __expf(a.w - nm1);
                ts0 += p.x + p.z;
                ts1 += p.y + p.w;
                float4 pt;
                pt.x = f2tf32f(p.x); pt.y = f2tf32f(p.y);
                pt.z = f2tf32f(p.z); pt.w = f2tf32f(p.w);
#pragma unroll
                for (int j = 0; j < NA; j++)
                    mma_tf32_16x8x8(acc[i][j], pt, bF[ka][j]);
            }
            ts0 += __shfl_xor_sync(0xffffffffu, ts0, 1);
            ts0 += __shfl_xor_sync(0xffffffffu, ts0, 2);
            ts1 += __shfl_xor_sync(0xffffffffu, ts1, 1);
            ts1 += __shfl_xor_sync(0xffffffffu, ts1, 2);
            lrun[i][0] += ts0; lrun[i][1] += ts1;
        }
        __syncthreads();
    }

    // ---- epilogue: normalize by l, store ----
    const int m_base = mt * 128 + wm * (MA * 16);
    const int n_base = wn * (NA * 8);
#pragma unroll
    for (int i = 0; i < MA; i++) {
        int row0 = m_base + i * 16 + g;
        float inv0 = 1.f / lrun[i][0];
        float inv1 = 1.f / lrun[i][1];
#pragma unroll
        for (int j = 0; j < NA; j++) {
            int col = n_base + j * 8 + lq * 2;
            float2 t0 = make_float2(acc[i][j][0] * inv0, acc[i][j][1] * inv0);
            float2 t1 = make_float2(acc[i][j][2] * inv1, acc[i][j][3] * inv1);
            *reinterpret_cast<float2*>(&Cz[(long long)row0 * CC + col]) = t0;
            *reinterpret_cast<float2*>(&Cz[(long long)(row0 + 8) * CC + col]) = t1;
        }
    }
}

// ---------------------------------------------------------------------------
extern "C" void kernel_launch(void* const* d_in, const int* in_sizes, int n_in,
                              void* d_out, int out_size)
{
    const float* x  = (const float*)d_in[0];
    const float* Wv = (const float*)d_in[1];
    const float* bv = (const float*)d_in[2];
    const float* Wl = (const float*)d_in[3];
    const float* Wc = (const float*)d_in[4];
    const float* bc = (const float*)d_in[5];
    const float* Wp = (const float*)d_in[6];
    const float* bp = (const float*)d_in[7];
    float* out = (float*)d_out;

    float *v_p, *u_p, *att2_p, *wcl_p, *y_p;
    cudaGetSymbolAddress((void**)&v_p,    g_v);
    cudaGetSymbolAddress((void**)&u_p,    g_u);
    cudaGetSymbolAddress((void**)&att2_p, g_att2);
    cudaGetSymbolAddress((void**)&wcl_p,  g_wcl);
    cudaGetSymbolAddress((void**)&y_p,    g_y);

    const long long sTT  = (long long)TT * TT;
    const long long sBTC = (long long)TT * CC;

    // 1) Wcl = Wc @ Wl   (tf32 NN)
    gemm_mma_k<128,2,4,false,false,false><<<dim3(8,8,1),256>>>(
        Wc, Wl, nullptr, wcl_p,
        TT, TT, TT, TT,
        0,0, 0,0, 0,0, 1, 1.0f);

    // 2) v = x @ Wv^T + bv   (tf32 NT)
    gemm_mma_k<128,2,4,true,false,false><<<dim3(CC/128, (BB*TT)/128, 1),256>>>(
        x, Wv, bv, v_p,
        CC, CC, CC, CC,
        0,0, 0,0, 0,0, 1, 1.0f);

    // 3) u[b] = Wcl @ v[b]   (tf32 NN, head-merged N=768)
    gemm_mma_k<128,2,4,false,false,false><<<dim3(CC/128, 8, BB),256>>>(
        wcl_p, v_p, nullptr, u_p,
        TT, TT, CC, CC,
        0,0, sBTC,0, sBTC,0, 1, 1.0f);

    // 4) att2 = vh @ uh^T / 8 + bc   (tf32 NT, K=64, causal tile skip; raw logits)
    gemm_mma_k<128,2,4,true,true,false><<<dim3(8,8,BB*NHH),256>>>(
        v_p, u_p, bc, att2_p,
        HDD, CC, CC, TT,
        sBTC, HDD, sBTC, HDD, (long long)NHH*sTT, sTT,
        NHH, 0.125f);

    // 5+6) y = softmax_causal(att2) @ vh   (fused online softmax + tf32 MMA)
    attnv_fused_k<<<dim3(1, 8, BB*NHH), 256>>>(att2_p, v_p, y_p);

    // 7) out = y @ Wp^T + bp   (tf32 NT)
    gemm_mma_k<128,2,4,true,false,false><<<dim3(CC/128, (BB*TT)/128, 1),256>>>(
        y_p, Wp, bp, out,
        CC, CC, CC, CC,
        0,0, 0,0, 0,0, 1, 1.0f);
}

// round 10
// speedup vs baseline: 4.4560x; 1.1404x over previous
#include <cuda_runtime.h>
#include <math.h>
#include <stdint.h>

// Problem constants
#define BB 8
#define TT 1024
#define CC 768
#define NHH 12
#define HDD 64

// Scratch (static __device__ arrays: no allocation allowed)
__device__ float g_v  [BB * TT * CC];   // value projection [B,T,C]
__device__ float g_u  [BB * TT * CC];   // u = Wcl @ v  [B,T,C]
__device__ float g_wcl[TT * TT];        // Wc @ Wl
__device__ float g_y  [BB * TT * CC];   // attention output [B,T,C]

// ===========================================================================
// tf32 helpers (base sm_80+ ISA — harness compiles compute_103, no tcgen05)
// ===========================================================================
__device__ __forceinline__ float f2tf32f(float x) {
    uint32_t u;
    asm("cvt.rna.tf32.f32 %0, %1;" : "=r"(u) : "f"(x));
    return __uint_as_float(u);
}

__device__ __forceinline__ void mma_tf32_16x8x8(
    float* d, const float4& a, const float2& b)
{
    asm volatile(
        "mma.sync.aligned.m16n8k8.row.col.f32.tf32.tf32.f32 "
        "{%0,%1,%2,%3}, {%4,%5,%6,%7}, {%8,%9}, {%0,%1,%2,%3};"
        : "+f"(d[0]), "+f"(d[1]), "+f"(d[2]), "+f"(d[3])
        : "r"(__float_as_uint(a.x)), "r"(__float_as_uint(a.y)),
          "r"(__float_as_uint(a.z)), "r"(__float_as_uint(a.w)),
          "r"(__float_as_uint(b.x)), "r"(__float_as_uint(b.y)));
}

// ===========================================================================
// Generic batched tf32 mma.sync GEMM (engine unchanged; used for steps 1,2,3,7)
// ===========================================================================
template<int BN, int WM, int WN, bool TB, bool SKIP_OUT, bool SKIP_K>
__global__ void __launch_bounds__(256)
gemm_mma_k(const float* __restrict__ A, const float* __restrict__ Bm,
           const float* __restrict__ bias, float* __restrict__ Cm,
           int K, int lda, int ldb, int ldc,
           long long sAb, long long sAh, long long sBb, long long sBh,
           long long sCb, long long sCh, int batchH, float alpha)
{
    constexpr int BM = 128, BK = 32;
    constexpr int MA = BM / WM / 16;
    constexpr int NA = BN / WN / 8;
    static_assert(WM * WN == 8, "8 warps");

    const int nt = blockIdx.x, mt = blockIdx.y;
    if (SKIP_OUT && nt > mt) return;
    const int z = blockIdx.z;
    const int b = z / batchH, h = z % batchH;
    const float* Az = A + b * sAb + h * sAh + (long long)mt * BM * lda;
    const float* Bz = Bm + b * sBb + h * sBh
                    + (TB ? (long long)nt * BN * ldb : (long long)nt * BN);
    float* Cz = Cm + b * sCb + h * sCh;

    __shared__ float sA[4][8][32][4];
    __shared__ float sB[4][BN / 8][32][2];

    const int tid = threadIdx.x, lane = tid & 31, w = tid >> 5;
    const int wm = w / WN, wn = w % WN;

    float acc[MA][NA][4];
#pragma unroll
    for (int i = 0; i < MA; i++)
#pragma unroll
        for (int j = 0; j < NA; j++)
#pragma unroll
            for (int r = 0; r < 4; r++) acc[i][j][r] = 0.f;

    const int kmax = SKIP_K ? (mt + 1) * BM : K;

    for (int k0 = 0; k0 < kmax; k0 += BK) {
#pragma unroll
        for (int i = 0; i < 4; i++) {
            int v = tid + i * 256;
            int row = v >> 3, c4 = v & 7;
            int ka = c4 >> 1;
            int r = (c4 & 1) * 2 + ((row >> 3) & 1);
            int ma = row >> 4, laneA = (row & 7) * 4;
            float4 t = *reinterpret_cast<const float4*>(
                &Az[(long long)row * lda + k0 + c4 * 4]);
            sA[ka][ma][laneA + 0][r] = f2tf32f(t.x);
            sA[ka][ma][laneA + 1][r] = f2tf32f(t.y);
            sA[ka][ma][laneA + 2][r] = f2tf32f(t.z);
            sA[ka][ma][laneA + 3][r] = f2tf32f(t.w);
        }
        if constexpr (TB) {
#pragma unroll
            for (int i = 0; i < BN / 32; i++) {
                int v = tid + i * 256;
                int n = v >> 3, c4 = v & 7;
                int ka = c4 >> 1, r = c4 & 1;
                int na = n >> 3, laneB = (n & 7) * 4;
                float4 t = *reinterpret_cast<const float4*>(
                    &Bz[(long long)n * ldb + k0 + c4 * 4]);
                sB[ka][na][laneB + 0][r] = f2tf32f(t.x);
                sB[ka][na][laneB + 1][r] = f2tf32f(t.y);
                sB[ka][na][laneB + 2][r] = f2tf32f(t.z);
                sB[ka][na][laneB + 3][r] = f2tf32f(t.w);
            }
        } else {
#pragma unroll
            for (int i = 0; i < BN / 32; i++) {
                int v = tid + i * 256;
                int krow = v / (BN / 4);
                int nc = (v % (BN / 4)) * 4;
                int ka = krow >> 3, kc = krow & 7;
                int r = kc >> 2, lc = kc & 3;
                int na = nc >> 3, nb = nc & 7;
                float4 t = *reinterpret_cast<const float4*>(
                    &Bz[(long long)(k0 + krow) * ldb + nc]);
                sB[ka][na][(nb + 0) * 4 + lc][r] = f2tf32f(t.x);
                sB[ka][na][(nb + 1) * 4 + lc][r] = f2tf32f(t.y);
                sB[ka][na][(nb + 2) * 4 + lc][r] = f2tf32f(t.z);
                sB[ka][na][(nb + 3) * 4 + lc][r] = f2tf32f(t.w);
            }
        }
        __syncthreads();

#pragma unroll
        for (int ka = 0; ka < 4; ka++) {
            float4 aF[MA];
            float2 bF[NA];
#pragma unroll
            for (int i = 0; i < MA; i++)
                aF[i] = *reinterpret_cast<const float4*>(&sA[ka][wm * MA + i][lane][0]);
#pragma unroll
            for (int j = 0; j < NA; j++)
                bF[j] = *reinterpret_cast<const float2*>(&sB[ka][wn * NA + j][lane][0]);
#pragma unroll
            for (int i = 0; i < MA; i++)
#pragma unroll
                for (int j = 0; j < NA; j++)
                    mma_tf32_16x8x8(acc[i][j], aF[i], bF[j]);
        }
        __syncthreads();
    }

    const int m_base = mt * BM + wm * (MA * 16);
    const int n_base = nt * BN + wn * (NA * 8);
#pragma unroll
    for (int i = 0; i < MA; i++) {
        int row0 = m_base + i * 16 + (lane >> 2);
#pragma unroll
        for (int j = 0; j < NA; j++) {
            int col = n_base + j * 8 + (lane & 3) * 2;
            float b0 = bias ? bias[col] : 0.f;
            float b1 = bias ? bias[col + 1] : 0.f;
            float2 t0 = make_float2(acc[i][j][0] * alpha + b0,
                                    acc[i][j][1] * alpha + b1);
            float2 t1 = make_float2(acc[i][j][2] * alpha + b0,
                                    acc[i][j][3] * alpha + b1);
            *reinterpret_cast<float2*>(&Cz[(long long)row0 * ldc + col]) = t0;
            *reinterpret_cast<float2*>(&Cz[(long long)(row0 + 8) * ldc + col]) = t1;
        }
    }
}

// ===========================================================================
// Flash kernel: steps 4+5+6 fused. Per (z, mt):
//   S = qtile @ u_j^T / 8 + bc   (tf32 mma, K=64)
//   online causal softmax on S (C-frags, intra-warp stats)
//   P -> smem (A-frag layout), y += P @ v_j (tf32 mma, K=128)
// 8 warps, WM=8/WN=1 in BOTH phases: warp w owns rows w*16..w*16+15 of S and y,
// and reads only the sP region it wrote -> no intra-tile syncthreads.
// smem (dynamic): sQ 32K | sU 32K | sV 32K | sP 64K | sBc 4K = 164 KB.
// ===========================================================================
#define FLASH_SMEM_FLOATS 41984   // 8192+8192+8192+16384+1024
#define FLASH_SMEM_BYTES  (FLASH_SMEM_FLOATS * 4)

__global__ void __launch_bounds__(256)
flash_attn_k(const float* __restrict__ vv, const float* __restrict__ uu,
             const float* __restrict__ bc, float* __restrict__ yy)
{
    const int mt = 7 - blockIdx.x;          // heavy tiles first
    const int z = blockIdx.y;
    const int b = z / NHH, h = z % NHH;

    const float* Qg = vv + ((long long)(b * TT + mt * 128)) * CC + h * HDD;
    const float* Ub = uu + (long long)b * TT * CC + h * HDD;
    const float* Vb = vv + (long long)b * TT * CC + h * HDD;
    float* Cz = yy + (long long)b * TT * CC + h * HDD;

    extern __shared__ float sm[];
    float* sQ  = sm;            // [ka8][ma8][lane32][r4]
    float* sU  = sm + 8192;     // [ka8][na16][lane32][r2]
    float* sV  = sm + 16384;    // [ka16][na8][lane32][r2]
    float* sP  = sm + 24576;    // [ka16][ma8][lane32][r4]
    float* sBc = sm + 40960;    // [1024]

    const int tid = threadIdx.x, lane = tid & 31, w = tid >> 5;
    const int g = lane >> 2, lq = lane & 3;

    // ---- load q tile (128 x 64) into A-frag layout; bc row ----
#pragma unroll
    for (int i = 0; i < 8; i++) {
        int v = tid + i * 256;
        int row = v >> 4, c4 = v & 15;       // c4: float4 within 64 k
        int ka = c4 >> 1;
        int r = (c4 & 1) * 2 + ((row >> 3) & 1);
        int base = ((ka * 8 + (row >> 4)) * 32 + (row & 7) * 4) * 4 + r;
        float4 t = *reinterpret_cast<const float4*>(&Qg[(long long)row * CC + c4 * 4]);
        sQ[base + 0 * 4] = f2tf32f(t.x);
        sQ[base + 1 * 4] = f2tf32f(t.y);
        sQ[base + 2 * 4] = f2tf32f(t.z);
        sQ[base + 3 * 4] = f2tf32f(t.w);
    }
    for (int i = tid; i < TT; i += 256) sBc[i] = bc[i];

    float yacc[8][4];
    float mrun0 = -INFINITY, mrun1 = -INFINITY, lrun0 = 0.f, lrun1 = 0.f;
#pragma unroll
    for (int j = 0; j < 8; j++)
#pragma unroll
        for (int r = 0; r < 4; r++) yacc[j][r] = 0.f;

    __syncthreads();

    for (int jt = 0; jt <= mt; jt++) {
        const float* Uj = Ub + (long long)(jt * 128) * CC;
        const float* Vj = Vb + (long long)(jt * 128) * CC;
        // ---- load u_j tile (128n x 64k) B-frag (TB) ----
#pragma unroll
        for (int i = 0; i < 8; i++) {
            int v = tid + i * 256;
            int n = v >> 4, c4 = v & 15;
            int ka = c4 >> 1, r = c4 & 1;
            int base = ((ka * 16 + (n >> 3)) * 32 + (n & 7) * 4) * 2 + r;
            float4 t = *reinterpret_cast<const float4*>(&Uj[(long long)n * CC + c4 * 4]);
            sU[base + 0 * 2] = f2tf32f(t.x);
            sU[base + 1 * 2] = f2tf32f(t.y);
            sU[base + 2 * 2] = f2tf32f(t.z);
            sU[base + 3 * 2] = f2tf32f(t.w);
        }
        // ---- load v_j tile (128k x 64n) B-frag (NN) ----
#pragma unroll
        for (int i = 0; i < 8; i++) {
            int v = tid + i * 256;
            int krow = v >> 4;
            int nc = (v & 15) * 4;
            int ka = krow >> 3, kc = krow & 7;
            int r = kc >> 2, lc = kc & 3;
            int na = nc >> 3, nb = nc & 7;
            float4 t = *reinterpret_cast<const float4*>(&Vj[(long long)krow * CC + nc]);
            sV[((ka * 8 + na) * 32 + (nb + 0) * 4 + lc) * 2 + r] = f2tf32f(t.x);
            sV[((ka * 8 + na) * 32 + (nb + 1) * 4 + lc) * 2 + r] = f2tf32f(t.y);
            sV[((ka * 8 + na) * 32 + (nb + 2) * 4 + lc) * 2 + r] = f2tf32f(t.z);
            sV[((ka * 8 + na) * 32 + (nb + 3) * 4 + lc) * 2 + r] = f2tf32f(t.w);
        }
        __syncthreads();

        // ---- phase A: S = q @ u_j^T  (warp w: rows w*16..+15, all 128 cols) ----
        float sAcc[16][4];
#pragma unroll
        for (int na = 0; na < 16; na++)
#pragma unroll
            for (int r = 0; r < 4; r++) sAcc[na][r] = 0.f;
#pragma unroll
        for (int ka = 0; ka < 8; ka++) {
            float4 aF = *reinterpret_cast<const float4*>(&sQ[((ka * 8 + w) * 32 + lane) * 4]);
#pragma unroll
            for (int na = 0; na < 16; na++) {
                float2 bF = *reinterpret_cast<const float2*>(&sU[((ka * 16 + na) * 32 + lane) * 2]);
                mma_tf32_16x8x8(sAcc[na], aF, bF);
            }
        }

        // ---- phase B: scale+bias, causal mask, online softmax, P -> sP ----
        const bool diag = (jt == mt);
        const int r0 = w * 16 + g;           // local row (a0/a1), +8 for a2/a3
        float s[16][4];
        float tm0 = -INFINITY, tm1 = -INFINITY;
#pragma unroll
        for (int na = 0; na < 16; na++) {
            int c0 = na * 8 + 2 * lq;
            float2 bb = *reinterpret_cast<const float2*>(&sBc[jt * 128 + c0]);
            float s0 = sAcc[na][0] * 0.125f + bb.x;
            float s1 = sAcc[na][1] * 0.125f + bb.y;
            float s2 = sAcc[na][2] * 0.125f + bb.x;
            float s3 = sAcc[na][3] * 0.125f + bb.y;
            if (diag) {
                if (c0 > r0)         s0 = -1e30f;
                if (c0 + 1 > r0)     s1 = -1e30f;
                if (c0 > r0 + 8)     s2 = -1e30f;
                if (c0 + 1 > r0 + 8) s3 = -1e30f;
            }
            s[na][0] = s0; s[na][1] = s1; s[na][2] = s2; s[na][3] = s3;
            tm0 = fmaxf(tm0, fmaxf(s0, s1));
            tm1 = fmaxf(tm1, fmaxf(s2, s3));
        }
        tm0 = fmaxf(tm0, __shfl_xor_sync(0xffffffffu, tm0, 1));
        tm0 = fmaxf(tm0, __shfl_xor_sync(0xffffffffu, tm0, 2));
        tm1 = fmaxf(tm1, __shfl_xor_sync(0xffffffffu, tm1, 1));
        tm1 = fmaxf(tm1, __shfl_xor_sync(0xffffffffu, tm1, 2));

        const float nm0 = fmaxf(mrun0, tm0);
        const float nm1 = fmaxf(mrun1, tm1);
        const float sc0 = __expf(mrun0 - nm0);
        const float sc1 = __expf(mrun1 - nm1);
        mrun0 = nm0; mrun1 = nm1;
        lrun0 *= sc0; lrun1 *= sc1;
#pragma unroll
        for (int j = 0; j < 8; j++) {
            yacc[j][0] *= sc0; yacc[j][1] *= sc0;
            yacc[j][2] *= sc1; yacc[j][3] *= sc1;
        }

        float ts0 = 0.f, ts1 = 0.f;
        const int lane0 = g * 4 + (lq & 1) * 2;     // kc = 2lq
        const int rA = (lq >> 1) * 2;
#pragma unroll
        for (int na = 0; na < 16; na++) {
            float p0 = __expf(s[na][0] - nm0);
            float p1 = __expf(s[na][1] - nm0);
            float p2 = __expf(s[na][2] - nm1);
            float p3 = __expf(s[na][3] - nm1);
            ts0 += p0 + p1;
            ts1 += p2 + p3;
            // P A-frag scatter: ka_p = na; rows w*16+g / +8 -> r parity
            float* pb = &sP[((na * 8 + w) * 32 + lane0) * 4 + rA];
            *reinterpret_cast<float2*>(pb)     = make_float2(f2tf32f(p0), f2tf32f(p2));
            *reinterpret_cast<float2*>(pb + 4) = make_float2(f2tf32f(p1), f2tf32f(p3));
        }
        ts0 += __shfl_xor_sync(0xffffffffu, ts0, 1);
        ts0 += __shfl_xor_sync(0xffffffffu, ts0, 2);
        ts1 += __shfl_xor_sync(0xffffffffu, ts1, 1);
        ts1 += __shfl_xor_sync(0xffffffffu, ts1, 2);
        lrun0 += ts0; lrun1 += ts1;

        // ---- phase C: y += P @ v_j (warp reads its own sP rows) ----
#pragma unroll
        for (int ka = 0; ka < 16; ka++) {
            float4 aP = *reinterpret_cast<const float4*>(&sP[((ka * 8 + w) * 32 + lane) * 4]);
#pragma unroll
            for (int na = 0; na < 8; na++) {
                float2 bF = *reinterpret_cast<const float2*>(&sV[((ka * 8 + na) * 32 + lane) * 2]);
                mma_tf32_16x8x8(yacc[na], aP, bF);
            }
        }
        __syncthreads();   // before next iteration overwrites sU/sV
    }

    // ---- epilogue: normalize, store ----
    const int row0 = mt * 128 + w * 16 + g;
    const float inv0 = 1.f / lrun0;
    const float inv1 = 1.f / lrun1;
#pragma unroll
    for (int j = 0; j < 8; j++) {
        int col = j * 8 + lq * 2;
        float2 t0 = make_float2(yacc[j][0] * inv0, yacc[j][1] * inv0);
        float2 t1 = make_float2(yacc[j][2] * inv1, yacc[j][3] * inv1);
        *reinterpret_cast<float2*>(&Cz[(long long)row0 * CC + col]) = t0;
        *reinterpret_cast<float2*>(&Cz[(long long)(row0 + 8) * CC + col]) = t1;
    }
}

// ---------------------------------------------------------------------------
extern "C" void kernel_launch(void* const* d_in, const int* in_sizes, int n_in,
                              void* d_out, int out_size)
{
    const float* x  = (const float*)d_in[0];
    const float* Wv = (const float*)d_in[1];
    const float* bv = (const float*)d_in[2];
    const float* Wl = (const float*)d_in[3];
    const float* Wc = (const float*)d_in[4];
    const float* bc = (const float*)d_in[5];
    const float* Wp = (const float*)d_in[6];
    const float* bp = (const float*)d_in[7];
    float* out = (float*)d_out;

    float *v_p, *u_p, *wcl_p, *y_p;
    cudaGetSymbolAddress((void**)&v_p,   g_v);
    cudaGetSymbolAddress((void**)&u_p,   g_u);
    cudaGetSymbolAddress((void**)&wcl_p, g_wcl);
    cudaGetSymbolAddress((void**)&y_p,   g_y);

    const long long sBTC = (long long)TT * CC;

    cudaFuncSetAttribute(flash_attn_k,
                         cudaFuncAttributeMaxDynamicSharedMemorySize,
                         FLASH_SMEM_BYTES);

    // 1) Wcl = Wc @ Wl   (tf32 NN)
    gemm_mma_k<128,2,4,false,false,false><<<dim3(8,8,1),256>>>(
        Wc, Wl, nullptr, wcl_p,
        TT, TT, TT, TT,
        0,0, 0,0, 0,0, 1, 1.0f);

    // 2) v = x @ Wv^T + bv   (tf32 NT)
    gemm_mma_k<128,2,4,true,false,false><<<dim3(CC/128, (BB*TT)/128, 1),256>>>(
        x, Wv, bv, v_p,
        CC, CC, CC, CC,
        0,0, 0,0, 0,0, 1, 1.0f);

    // 3) u[b] = Wcl @ v[b]   (tf32 NN, head-merged N=768)
    gemm_mma_k<128,2,4,false,false,false><<<dim3(CC/128, 8, BB),256>>>(
        wcl_p, v_p, nullptr, u_p,
        TT, TT, CC, CC,
        0,0, sBTC,0, sBTC,0, 1, 1.0f);

    // 4+5+6) y = softmax_causal(vh @ uh^T/8 + bc) @ vh   — fully fused flash
    flash_attn_k<<<dim3(8, BB*NHH), 256, FLASH_SMEM_BYTES>>>(
        v_p, u_p, bc, y_p);

    // 7) out = y @ Wp^T + bp   (tf32 NT)
    gemm_mma_k<128,2,4,true,false,false><<<dim3(CC/128, (BB*TT)/128, 1),256>>>(
        y_p, Wp, bp, out,
        CC, CC, CC, CC,
        0,0, 0,0, 0,0, 1, 1.0f);
}